// round 1
// baseline (speedup 1.0000x reference)
#include <cuda_runtime.h>
#include <cuda_bf16.h>
#include <math.h>

// Problem constants
#define M_ROWS 8192      // B*H*W = 32*16*16
#define N_E    8192
#define E_DIM  512

// Output layout (flattened tuple, fp32):
// [0]        loss
// [1]        constrative_loss
// [2]        loss_kl
// [3 ..)     encoding_indices_prob  (M_ROWS * N_E)
// OFF_D      d                      (M_ROWS * N_E)
// OFF_ZQ     z_q_st                 (M_ROWS * E_DIM)
// OFF_PERP   perplexity             (1)
// OFF_MINE   min_encodings          (M_ROWS * N_E)
// OFF_IDX    min_encoding_indices   (M_ROWS)
#define OFF_PROB ((size_t)3)
#define OFF_D    (OFF_PROB + (size_t)M_ROWS * N_E)
#define OFF_ZQ   (OFF_D    + (size_t)M_ROWS * N_E)
#define OFF_PERP (OFF_ZQ   + (size_t)M_ROWS * E_DIM)
#define OFF_MINE (OFF_PERP + 1)
#define OFF_IDX  (OFF_MINE + (size_t)M_ROWS * N_E)

// Device scratch (no dynamic allocation allowed)
static __device__ float g_cb[(size_t)N_E * E_DIM];   // normalized codebook, 16 MB
static __device__ float g_cbnorm[N_E];
static __device__ float g_znorm[M_ROWS];
static __device__ int   g_idx[M_ROWS];
static __device__ int   g_counts[N_E];
static __device__ float g_cos[M_ROWS];

// ---------------------------------------------------------------------------
// Codebook normalization: cb = w / ||w||, cb_norm = ||cb|| (recomputed)
// ---------------------------------------------------------------------------
__global__ __launch_bounds__(256) void prep_cb_kernel(const float* __restrict__ w) {
    int r = blockIdx.x;
    int t = threadIdx.x;
    const float* row = w + (size_t)r * E_DIM;
    float v0 = row[t];
    float v1 = row[t + 256];

    __shared__ float sm[256];
    sm[t] = v0 * v0 + v1 * v1;
    __syncthreads();
    #pragma unroll
    for (int s = 128; s > 0; s >>= 1) {
        if (t < s) sm[t] += sm[t + s];
        __syncthreads();
    }
    float norm = sqrtf(sm[0]);
    __syncthreads();

    float c0 = v0 / norm;
    float c1 = v1 / norm;
    g_cb[(size_t)r * E_DIM + t]       = c0;
    g_cb[(size_t)r * E_DIM + t + 256] = c1;

    sm[t] = c0 * c0 + c1 * c1;
    __syncthreads();
    #pragma unroll
    for (int s = 128; s > 0; s >>= 1) {
        if (t < s) sm[t] += sm[t + s];
        __syncthreads();
    }
    if (t == 0) g_cbnorm[r] = sqrtf(sm[0]);
}

// ---------------------------------------------------------------------------
// z row norms
// ---------------------------------------------------------------------------
__global__ __launch_bounds__(256) void prep_z_kernel(const float* __restrict__ z) {
    int r = blockIdx.x;
    int t = threadIdx.x;
    const float* row = z + (size_t)r * E_DIM;
    float v0 = row[t];
    float v1 = row[t + 256];

    __shared__ float sm[256];
    sm[t] = v0 * v0 + v1 * v1;
    __syncthreads();
    #pragma unroll
    for (int s = 128; s > 0; s >>= 1) {
        if (t < s) sm[t] += sm[t + s];
        __syncthreads();
    }
    if (t == 0) g_znorm[r] = sqrtf(sm[0]);
}

__global__ void zero_counts_kernel() {
    int i = blockIdx.x * 256 + threadIdx.x;
    if (i < N_E) g_counts[i] = 0;
}

// ---------------------------------------------------------------------------
// SGEMM: d[i][j] = dot(z_i, cb_j) / (znorm_i * cbnorm_j + 1e-6)
// 128x128 block tile, BK=16, 8x8 per thread, 256 threads.
// ---------------------------------------------------------------------------
#define BM 128
#define BN 128
#define BK 16

__global__ __launch_bounds__(256) void sgemm_kernel(const float* __restrict__ Z,
                                                    float* __restrict__ out) {
    __shared__ float As[BK][BM];
    __shared__ float Bs[BK][BN];

    int tid = threadIdx.x;
    int tx = tid & 15;       // 0..15 -> column group
    int ty = tid >> 4;       // 0..15 -> row group
    int bx = blockIdx.x;     // N tile
    int by = blockIdx.y;     // M tile

    const float* Aptr = Z    + (size_t)(by * BM) * E_DIM;
    const float* Bptr = g_cb + (size_t)(bx * BN) * E_DIM;

    float acc[8][8];
    #pragma unroll
    for (int i = 0; i < 8; i++)
        #pragma unroll
        for (int j = 0; j < 8; j++) acc[i][j] = 0.0f;

    for (int k0 = 0; k0 < E_DIM; k0 += BK) {
        // cooperative loads: 128 rows x 16 cols per tile = 512 float4 slots
        #pragma unroll
        for (int s = 0; s < 2; s++) {
            int slot = tid + s * 256;         // 0..511
            int row  = slot >> 2;             // 0..127
            int kk   = (slot & 3) * 4;        // 0,4,8,12
            float4 va = *(const float4*)(Aptr + (size_t)row * E_DIM + k0 + kk);
            As[kk + 0][row] = va.x; As[kk + 1][row] = va.y;
            As[kk + 2][row] = va.z; As[kk + 3][row] = va.w;
            float4 vb = *(const float4*)(Bptr + (size_t)row * E_DIM + k0 + kk);
            Bs[kk + 0][row] = vb.x; Bs[kk + 1][row] = vb.y;
            Bs[kk + 2][row] = vb.z; Bs[kk + 3][row] = vb.w;
        }
        __syncthreads();

        #pragma unroll
        for (int kk = 0; kk < BK; kk++) {
            float a[8], b[8];
            #pragma unroll
            for (int i = 0; i < 8; i++) a[i] = As[kk][ty * 8 + i];
            #pragma unroll
            for (int j = 0; j < 8; j++) b[j] = Bs[kk][tx * 8 + j];
            #pragma unroll
            for (int i = 0; i < 8; i++)
                #pragma unroll
                for (int j = 0; j < 8; j++)
                    acc[i][j] += a[i] * b[j];
        }
        __syncthreads();
    }

    // epilogue: scale by 1/(znorm*cbnorm + 1e-6) and write scalar (OFF_D is
    // only 4B-aligned so no vector stores into out).
    int r0 = by * BM + ty * 8;
    int c0 = bx * BN + tx * 8;
    float zn[8], cn[8];
    #pragma unroll
    for (int i = 0; i < 8; i++) zn[i] = g_znorm[r0 + i];
    #pragma unroll
    for (int j = 0; j < 8; j++) cn[j] = g_cbnorm[c0 + j];

    float* D = out + OFF_D;
    #pragma unroll
    for (int i = 0; i < 8; i++) {
        float* drow = D + (size_t)(r0 + i) * N_E + c0;
        #pragma unroll
        for (int j = 0; j < 8; j++) {
            drow[j] = acc[i][j] / (zn[i] * cn[j] + 1e-6f);
        }
    }
}

// ---------------------------------------------------------------------------
// Fused per-row: max/argmax (first-index tie-break), histogram, index output,
// sum(exp), softmax write. One read of d, one write of prob.
// ---------------------------------------------------------------------------
__global__ __launch_bounds__(256) void softmax_kernel(float* __restrict__ out) {
    __shared__ float srow[N_E];
    __shared__ float sred[256];
    __shared__ int   sidx[256];

    int r = blockIdx.x;
    int t = threadIdx.x;
    const float* drow = out + OFF_D + (size_t)r * N_E;

    for (int i = t; i < N_E; i += 256) srow[i] = drow[i];
    __syncthreads();

    // per-thread contiguous chunk of 32, strictly-greater keeps first max
    int base = t * 32;
    float best = srow[base];
    int bi = base;
    #pragma unroll 4
    for (int i = base + 1; i < base + 32; i++) {
        float v = srow[i];
        if (v > best) { best = v; bi = i; }
    }
    sred[t] = best; sidx[t] = bi;
    __syncthreads();
    for (int s = 128; s > 0; s >>= 1) {
        if (t < s) {
            float v = sred[t + s]; int ii = sidx[t + s];
            if (v > sred[t] || (v == sred[t] && ii < sidx[t])) {
                sred[t] = v; sidx[t] = ii;
            }
        }
        __syncthreads();
    }
    float mx = sred[0];
    int idx  = sidx[0];
    if (t == 0) {
        g_idx[r] = idx;
        atomicAdd(&g_counts[idx], 1);
        out[OFF_IDX + r] = (float)idx;
    }
    __syncthreads();

    float sum = 0.0f;
    #pragma unroll 4
    for (int i = base; i < base + 32; i++) sum += expf(srow[i] - mx);
    sred[t] = sum;
    __syncthreads();
    for (int s = 128; s > 0; s >>= 1) {
        if (t < s) sred[t] += sred[t + s];
        __syncthreads();
    }
    float inv = 1.0f / sred[0];

    float* prow = out + OFF_PROB + (size_t)r * N_E;
    for (int i = t; i < N_E; i += 256) prow[i] = expf(srow[i] - mx) * inv;
}

// ---------------------------------------------------------------------------
// one-hot scatter (region pre-zeroed by memset)
// ---------------------------------------------------------------------------
__global__ void onehot_kernel(float* __restrict__ out) {
    int i = blockIdx.x * 256 + threadIdx.x;
    if (i < M_ROWS) {
        out[OFF_MINE + (size_t)i * N_E + g_idx[i]] = 1.0f;
    }
}

// ---------------------------------------------------------------------------
// z_q gather, z_q_st = z + (z_q - z), per-row cosine
// ---------------------------------------------------------------------------
__global__ __launch_bounds__(128) void zq_kernel(const float* __restrict__ Z,
                                                 float* __restrict__ out) {
    int r = blockIdx.x;
    int t = threadIdx.x;
    int j = g_idx[r];
    const float* zr = Z    + (size_t)r * E_DIM;
    const float* cr = g_cb + (size_t)j * E_DIM;
    float* o = out + OFF_ZQ + (size_t)r * E_DIM;

    float dot = 0.0f, nc = 0.0f, nz = 0.0f;
    #pragma unroll
    for (int i = t; i < E_DIM; i += 128) {
        float zv = zr[i];
        float cv = cr[i];
        o[i] = zv + (cv - zv);             // matches z + sg(z_q - z)
        dot += zv * cv;
        nc  += cv * cv;
        nz  += zv * zv;
    }

    __shared__ float sd[128], sc[128], sz[128];
    sd[t] = dot; sc[t] = nc; sz[t] = nz;
    __syncthreads();
    for (int s = 64; s > 0; s >>= 1) {
        if (t < s) { sd[t] += sd[t + s]; sc[t] += sc[t + s]; sz[t] += sz[t + s]; }
        __syncthreads();
    }
    if (t == 0) {
        float c = sd[0] / (fmaxf(sqrtf(sc[0]), 1e-8f) * fmaxf(sqrtf(sz[0]), 1e-8f));
        g_cos[r] = c;
    }
}

// ---------------------------------------------------------------------------
// Scalars: loss, constrative_loss(=0), loss_kl, perplexity
// ---------------------------------------------------------------------------
__global__ __launch_bounds__(256) void finalize_kernel(float* __restrict__ out) {
    int t = threadIdx.x;
    __shared__ float s1[256], s2[256], s3[256];

    float kl = 0.0f, ent = 0.0f, cs = 0.0f;
    const float invM = 1.0f / (float)M_ROWS;
    const float invNE = 1.0f / (float)N_E;
    for (int j = t; j < N_E; j += 256) {
        float em = (float)g_counts[j] * invM;
        kl  += em * logf(invNE / (em + 1e-6f));
        ent += em * logf(em + 1e-6f);
    }
    for (int j = t; j < M_ROWS; j += 256) cs += g_cos[j];

    s1[t] = kl; s2[t] = ent; s3[t] = cs;
    __syncthreads();
    for (int s = 128; s > 0; s >>= 1) {
        if (t < s) { s1[t] += s1[t + s]; s2[t] += s2[t + s]; s3[t] += s3[t + s]; }
        __syncthreads();
    }
    if (t == 0) {
        float loss_kl = -s1[0];
        float perp    = expf(-s2[0]);
        float mc      = s3[0] * invM;
        float loss    = (1.0f - mc) + 0.25f * (1.0f - mc);
        out[0] = loss;
        out[1] = 0.0f;           // constrative_loss
        out[2] = loss_kl;
        out[OFF_PERP] = perp;
    }
}

// ---------------------------------------------------------------------------
extern "C" void kernel_launch(void* const* d_in, const int* in_sizes, int n_in,
                              void* d_out, int out_size) {
    const float* z = (const float*)d_in[0];      // (32,16,16,512) -> 8192x512
    const float* w = (const float*)d_in[1];      // (8192,512)
    float* out = (float*)d_out;

    prep_cb_kernel<<<N_E, 256>>>(w);
    prep_z_kernel<<<M_ROWS, 256>>>(z);
    zero_counts_kernel<<<(N_E + 255) / 256, 256>>>();

    dim3 grid(N_E / BN, M_ROWS / BM);
    sgemm_kernel<<<grid, 256>>>(z, out);

    softmax_kernel<<<M_ROWS, 256>>>(out);

    cudaMemsetAsync(out + OFF_MINE, 0, (size_t)M_ROWS * N_E * sizeof(float));
    onehot_kernel<<<(M_ROWS + 255) / 256, 256>>>(out);

    zq_kernel<<<M_ROWS, 128>>>(z, out);
    finalize_kernel<<<1, 256>>>(out);
}

// round 3
// speedup vs baseline: 3.5262x; 3.5262x over previous
#include <cuda_runtime.h>
#include <cuda_bf16.h>
#include <math.h>
#include <stdint.h>

// Problem constants
#define M_ROWS 8192      // B*H*W
#define N_E    8192
#define E_DIM  512

// Output layout (flattened tuple, fp32)
#define OFF_PROB ((size_t)3)
#define OFF_D    (OFF_PROB + (size_t)M_ROWS * N_E)
#define OFF_ZQ   (OFF_D    + (size_t)M_ROWS * N_E)
#define OFF_PERP (OFF_ZQ   + (size_t)M_ROWS * E_DIM)
#define OFF_MINE (OFF_PERP + 1)
#define OFF_IDX  (OFF_MINE + (size_t)M_ROWS * N_E)

// ---------------------------------------------------------------------------
// Device scratch (no dynamic allocation allowed)
// ---------------------------------------------------------------------------
static __device__ float g_cb[(size_t)N_E * E_DIM];
static __device__ float g_cbnorm[N_E];
static __device__ float g_znorm[M_ROWS];
static __device__ int   g_idx[M_ROWS];
static __device__ int   g_counts[N_E];
static __device__ float g_cos[M_ROWS];
// bf16 hi/lo splits for tensor-core GEMM
static __device__ __align__(16) __nv_bfloat16 g_zhi[(size_t)M_ROWS * E_DIM];
static __device__ __align__(16) __nv_bfloat16 g_zlo[(size_t)M_ROWS * E_DIM];
static __device__ __align__(16) __nv_bfloat16 g_bhi[(size_t)N_E   * E_DIM];
static __device__ __align__(16) __nv_bfloat16 g_blo[(size_t)N_E   * E_DIM];

// ---------------------------------------------------------------------------
// PTX helpers (base ISA only: mma.sync / ldmatrix / cp.async)
// ---------------------------------------------------------------------------
__device__ __forceinline__ uint32_t smem_u32(const void* p) {
    uint32_t a;
    asm("{ .reg .u64 t; cvta.to.shared.u64 t, %1; cvt.u32.u64 %0, t; }"
        : "=r"(a) : "l"(p));
    return a;
}
__device__ __forceinline__ void cp16(uint32_t saddr, const void* g) {
    asm volatile("cp.async.cg.shared.global [%0], [%1], 16;"
                 :: "r"(saddr), "l"(g) : "memory");
}
__device__ __forceinline__ void ldsm4(uint32_t* r, uint32_t addr) {
    asm volatile("ldmatrix.sync.aligned.m8n8.x4.shared.b16 {%0,%1,%2,%3}, [%4];"
                 : "=r"(r[0]), "=r"(r[1]), "=r"(r[2]), "=r"(r[3]) : "r"(addr));
}
__device__ __forceinline__ void mma_bf16(float* c, const uint32_t* a, const uint32_t* b) {
    asm volatile(
        "mma.sync.aligned.m16n8k16.row.col.f32.bf16.bf16.f32 "
        "{%0,%1,%2,%3}, {%4,%5,%6,%7}, {%8,%9}, {%0,%1,%2,%3};"
        : "+f"(c[0]), "+f"(c[1]), "+f"(c[2]), "+f"(c[3])
        : "r"(a[0]), "r"(a[1]), "r"(a[2]), "r"(a[3]), "r"(b[0]), "r"(b[1]));
}

// ---------------------------------------------------------------------------
// Codebook prep: cb = w/||w||, cb_norm = ||cb||, bf16 hi/lo split
// ---------------------------------------------------------------------------
__global__ __launch_bounds__(256) void prep_cb_kernel(const float* __restrict__ w) {
    int r = blockIdx.x;
    int t = threadIdx.x;
    const float* row = w + (size_t)r * E_DIM;
    float v0 = row[t];
    float v1 = row[t + 256];

    __shared__ float sm[256];
    sm[t] = v0 * v0 + v1 * v1;
    __syncthreads();
    #pragma unroll
    for (int s = 128; s > 0; s >>= 1) {
        if (t < s) sm[t] += sm[t + s];
        __syncthreads();
    }
    float norm = sqrtf(sm[0]);
    __syncthreads();

    float c0 = v0 / norm;
    float c1 = v1 / norm;
    size_t base = (size_t)r * E_DIM;
    g_cb[base + t]       = c0;
    g_cb[base + t + 256] = c1;

    __nv_bfloat16 h0 = __float2bfloat16(c0);
    __nv_bfloat16 h1 = __float2bfloat16(c1);
    g_bhi[base + t]       = h0;
    g_bhi[base + t + 256] = h1;
    g_blo[base + t]       = __float2bfloat16(c0 - __bfloat162float(h0));
    g_blo[base + t + 256] = __float2bfloat16(c1 - __bfloat162float(h1));

    sm[t] = c0 * c0 + c1 * c1;
    __syncthreads();
    #pragma unroll
    for (int s = 128; s > 0; s >>= 1) {
        if (t < s) sm[t] += sm[t + s];
        __syncthreads();
    }
    if (t == 0) g_cbnorm[r] = sqrtf(sm[0]);
}

// ---------------------------------------------------------------------------
// z prep: row norms + bf16 hi/lo split
// ---------------------------------------------------------------------------
__global__ __launch_bounds__(256) void prep_z_kernel(const float* __restrict__ z) {
    int r = blockIdx.x;
    int t = threadIdx.x;
    const float* row = z + (size_t)r * E_DIM;
    float v0 = row[t];
    float v1 = row[t + 256];

    size_t base = (size_t)r * E_DIM;
    __nv_bfloat16 h0 = __float2bfloat16(v0);
    __nv_bfloat16 h1 = __float2bfloat16(v1);
    g_zhi[base + t]       = h0;
    g_zhi[base + t + 256] = h1;
    g_zlo[base + t]       = __float2bfloat16(v0 - __bfloat162float(h0));
    g_zlo[base + t + 256] = __float2bfloat16(v1 - __bfloat162float(h1));

    __shared__ float sm[256];
    sm[t] = v0 * v0 + v1 * v1;
    __syncthreads();
    #pragma unroll
    for (int s = 128; s > 0; s >>= 1) {
        if (t < s) sm[t] += sm[t + s];
        __syncthreads();
    }
    if (t == 0) g_znorm[r] = sqrtf(sm[0]);
}

__global__ void zero_counts_kernel() {
    int i = blockIdx.x * 256 + threadIdx.x;
    if (i < N_E) g_counts[i] = 0;
}

// ---------------------------------------------------------------------------
// mma.sync GEMM (4-term bf16 split): tile 128x128, K chunks of 64,
// cp.async double buffer, 8 warps (4x2), warp tile 32x64.
// smem row stride 144B (pad) -> conflict-free ldmatrix.
// ---------------------------------------------------------------------------
#define BM 128
#define BN 128
#define KC 64
#define NCHUNK (E_DIM / KC)        // 8
#define STRIDE 144                 // bytes per 64-bf16 row (128 + 16 pad)
#define ARR_SZ (128 * STRIDE)      // 18432
#define STAGE_SZ (4 * ARR_SZ)      // 73728
#define GEMM_SMEM (2 * STAGE_SZ)   // 147456

__global__ __launch_bounds__(256, 1) void mma_gemm_kernel(float* __restrict__ out) {
    extern __shared__ char smem[];
    const uint32_t sbase = smem_u32(smem);
    const int tid = threadIdx.x;
    const int lane = tid & 31;
    const int wid = tid >> 5;
    const int wm = wid & 3;        // m-quadrant: 32 rows each
    const int wn = wid >> 2;       // n-half: 64 cols each
    const int r0 = blockIdx.y * BM;
    const int c0 = blockIdx.x * BN;

    float acc[2][8][4];
    #pragma unroll
    for (int a = 0; a < 2; a++)
        #pragma unroll
        for (int b = 0; b < 8; b++)
            #pragma unroll
            for (int e = 0; e < 4; e++) acc[a][b][e] = 0.0f;

    // ---- chunk loader (cp.async), all 256 threads ----
    auto load_chunk = [&](int c, int stage) {
        uint32_t sb = sbase + (uint32_t)stage * STAGE_SZ;
        #pragma unroll
        for (int i = 0; i < 4; i++) {
            int slot = tid + i * 256;      // 0..1023
            int row = slot >> 3;
            int u   = slot & 7;
            uint32_t so = (uint32_t)row * STRIDE + (uint32_t)u * 16;
            size_t ga = (size_t)(r0 + row) * E_DIM + c * KC + u * 8;
            size_t gb = (size_t)(c0 + row) * E_DIM + c * KC + u * 8;
            cp16(sb + so,              g_zhi + ga);
            cp16(sb + ARR_SZ + so,     g_zlo + ga);
            cp16(sb + 2 * ARR_SZ + so, g_bhi + gb);
            cp16(sb + 3 * ARR_SZ + so, g_blo + gb);
        }
        asm volatile("cp.async.commit_group;" ::: "memory");
    };

    // per-lane ldmatrix address components
    const uint32_t aRow  = (uint32_t)(wm * 32 + (lane & 15)) * STRIDE + ((lane >> 4) * 16);
    const uint32_t bRow  = (uint32_t)(wn * 64 + (lane & 7) + ((lane >> 4) << 3)) * STRIDE
                         + (((lane >> 3) & 1) * 16);

    auto compute = [&](int stage) {
        uint32_t sb = sbase + (uint32_t)stage * STAGE_SZ;
        uint32_t aHi = sb + aRow;
        uint32_t aLo = aHi + ARR_SZ;
        uint32_t bHi = sb + 2 * ARR_SZ + bRow;
        uint32_t bLo = bHi + ARR_SZ;
        #pragma unroll
        for (int ks = 0; ks < 4; ks++) {
            uint32_t ah[2][4], al[2][4];
            ldsm4(ah[0], aHi + ks * 32);
            ldsm4(ah[1], aHi + 16 * STRIDE + ks * 32);
            ldsm4(al[0], aLo + ks * 32);
            ldsm4(al[1], aLo + 16 * STRIDE + ks * 32);
            #pragma unroll
            for (int np = 0; np < 4; np++) {
                uint32_t bh[4], bl[4];
                ldsm4(bh, bHi + np * 16 * STRIDE + ks * 32);
                ldsm4(bl, bLo + np * 16 * STRIDE + ks * 32);
                #pragma unroll
                for (int mt = 0; mt < 2; mt++) {
                    #pragma unroll
                    for (int s = 0; s < 2; s++) {
                        float* a4 = acc[mt][np * 2 + s];
                        mma_bf16(a4, ah[mt], bh + 2 * s);   // hi*hi
                        mma_bf16(a4, al[mt], bh + 2 * s);   // lo*hi
                        mma_bf16(a4, ah[mt], bl + 2 * s);   // hi*lo
                        mma_bf16(a4, al[mt], bl + 2 * s);   // lo*lo
                    }
                }
            }
        }
    };

    // ---- pipelined mainloop ----
    load_chunk(0, 0);
    #pragma unroll 1
    for (int c = 0; c < NCHUNK; c++) {
        if (c + 1 < NCHUNK) {
            load_chunk(c + 1, (c + 1) & 1);
            asm volatile("cp.async.wait_group 1;" ::: "memory");
        } else {
            asm volatile("cp.async.wait_group 0;" ::: "memory");
        }
        __syncthreads();
        compute(c & 1);
        __syncthreads();
    }

    // ---- epilogue: scale + scalar stores (OFF_D only 4B-aligned) ----
    float* D = out + OFF_D;
    const int gr = lane >> 2;
    const int gc = (lane & 3) * 2;
    #pragma unroll
    for (int mt = 0; mt < 2; mt++) {
        int rA = r0 + wm * 32 + mt * 16 + gr;
        int rB = rA + 8;
        float znA = g_znorm[rA];
        float znB = g_znorm[rB];
        #pragma unroll
        for (int n8 = 0; n8 < 8; n8++) {
            int cc = c0 + wn * 64 + n8 * 8 + gc;
            float cn0 = g_cbnorm[cc];
            float cn1 = g_cbnorm[cc + 1];
            float* a4 = acc[mt][n8];
            D[(size_t)rA * N_E + cc]     = a4[0] / (znA * cn0 + 1e-6f);
            D[(size_t)rA * N_E + cc + 1] = a4[1] / (znA * cn1 + 1e-6f);
            D[(size_t)rB * N_E + cc]     = a4[2] / (znB * cn0 + 1e-6f);
            D[(size_t)rB * N_E + cc + 1] = a4[3] / (znB * cn1 + 1e-6f);
        }
    }
}

// ---------------------------------------------------------------------------
// Polynomial exp on [-1,1] (degree-10 Taylor, FMA pipe; avoids MUFU wall)
// ---------------------------------------------------------------------------
__device__ __forceinline__ float exp_poly(float x) {
    const float c10 = 2.7557319e-7f, c9 = 2.7557319e-6f, c8 = 2.4801587e-5f;
    const float c7 = 1.9841270e-4f,  c6 = 1.3888889e-3f, c5 = 8.3333333e-3f;
    const float c4 = 4.1666668e-2f,  c3 = 1.6666667e-1f, c2 = 0.5f;
    float p = c10;
    p = fmaf(p, x, c9);
    p = fmaf(p, x, c8);
    p = fmaf(p, x, c7);
    p = fmaf(p, x, c6);
    p = fmaf(p, x, c5);
    p = fmaf(p, x, c4);
    p = fmaf(p, x, c3);
    p = fmaf(p, x, c2);
    p = fmaf(p, x, 1.0f);
    p = fmaf(p, x, 1.0f);
    return p;
}

// ---------------------------------------------------------------------------
// Fused per-row: argmax (first-index tie-break), histogram, idx output,
// softmax via poly exp (no max shift; d in [-1,1] so range is safe and
// softmax is shift-invariant).
// ---------------------------------------------------------------------------
__global__ __launch_bounds__(256) void softmax_kernel(float* __restrict__ out) {
    __shared__ float sred[256];
    __shared__ int   sidx[256];

    int r = blockIdx.x;
    int t = threadIdx.x;
    const float* drow = out + OFF_D + (size_t)r * N_E;

    float e[32];
    float best = -2.0f;
    int bi = 0;
    float sum = 0.0f;
    #pragma unroll
    for (int j = 0; j < 32; j++) {
        int i = t + j * 256;
        float v = drow[i];
        if (v > best) { best = v; bi = i; }   // j ascending => first index kept
        float ev = exp_poly(v);
        e[j] = ev;
        sum += ev;
    }
    sred[t] = best; sidx[t] = bi;
    __syncthreads();
    for (int s = 128; s > 0; s >>= 1) {
        if (t < s) {
            float v = sred[t + s]; int ii = sidx[t + s];
            if (v > sred[t] || (v == sred[t] && ii < sidx[t])) {
                sred[t] = v; sidx[t] = ii;
            }
        }
        __syncthreads();
    }
    if (t == 0) {
        int idx = sidx[0];
        g_idx[r] = idx;
        atomicAdd(&g_counts[idx], 1);
        out[OFF_IDX + r] = (float)idx;
    }
    __syncthreads();

    sred[t] = sum;
    __syncthreads();
    for (int s = 128; s > 0; s >>= 1) {
        if (t < s) sred[t] += sred[t + s];
        __syncthreads();
    }
    float inv = 1.0f / sred[0];

    float* prow = out + OFF_PROB + (size_t)r * N_E;
    #pragma unroll
    for (int j = 0; j < 32; j++) prow[t + j * 256] = e[j] * inv;
}

// ---------------------------------------------------------------------------
__global__ void onehot_kernel(float* __restrict__ out) {
    int i = blockIdx.x * 256 + threadIdx.x;
    if (i < M_ROWS) {
        out[OFF_MINE + (size_t)i * N_E + g_idx[i]] = 1.0f;
    }
}

// ---------------------------------------------------------------------------
__global__ __launch_bounds__(128) void zq_kernel(const float* __restrict__ Z,
                                                 float* __restrict__ out) {
    int r = blockIdx.x;
    int t = threadIdx.x;
    int j = g_idx[r];
    const float* zr = Z    + (size_t)r * E_DIM;
    const float* cr = g_cb + (size_t)j * E_DIM;
    float* o = out + OFF_ZQ + (size_t)r * E_DIM;

    float dot = 0.0f, nc = 0.0f, nz = 0.0f;
    #pragma unroll
    for (int i = t; i < E_DIM; i += 128) {
        float zv = zr[i];
        float cv = cr[i];
        o[i] = zv + (cv - zv);
        dot += zv * cv;
        nc  += cv * cv;
        nz  += zv * zv;
    }
    __shared__ float sd_[128], sc_[128], sz_[128];
    sd_[t] = dot; sc_[t] = nc; sz_[t] = nz;
    __syncthreads();
    for (int s = 64; s > 0; s >>= 1) {
        if (t < s) { sd_[t] += sd_[t + s]; sc_[t] += sc_[t + s]; sz_[t] += sz_[t + s]; }
        __syncthreads();
    }
    if (t == 0) {
        g_cos[r] = sd_[0] / (fmaxf(sqrtf(sc_[0]), 1e-8f) * fmaxf(sqrtf(sz_[0]), 1e-8f));
    }
}

// ---------------------------------------------------------------------------
__global__ __launch_bounds__(256) void finalize_kernel(float* __restrict__ out) {
    int t = threadIdx.x;
    __shared__ float s1[256], s2[256], s3[256];

    float kl = 0.0f, ent = 0.0f, cs = 0.0f;
    const float invM  = 1.0f / (float)M_ROWS;
    const float invNE = 1.0f / (float)N_E;
    for (int j = t; j < N_E; j += 256) {
        float em = (float)g_counts[j] * invM;
        kl  += em * logf(invNE / (em + 1e-6f));
        ent += em * logf(em + 1e-6f);
    }
    for (int j = t; j < M_ROWS; j += 256) cs += g_cos[j];

    s1[t] = kl; s2[t] = ent; s3[t] = cs;
    __syncthreads();
    for (int s = 128; s > 0; s >>= 1) {
        if (t < s) { s1[t] += s1[t + s]; s2[t] += s2[t + s]; s3[t] += s3[t + s]; }
        __syncthreads();
    }
    if (t == 0) {
        float mc = s3[0] * invM;
        out[0] = (1.0f - mc) + 0.25f * (1.0f - mc);
        out[1] = 0.0f;
        out[2] = -s1[0];
        out[OFF_PERP] = expf(-s2[0]);
    }
}

// ---------------------------------------------------------------------------
extern "C" void kernel_launch(void* const* d_in, const int* in_sizes, int n_in,
                              void* d_out, int out_size) {
    const float* z = (const float*)d_in[0];
    const float* w = (const float*)d_in[1];
    float* out = (float*)d_out;

    cudaFuncSetAttribute(mma_gemm_kernel,
                         cudaFuncAttributeMaxDynamicSharedMemorySize, GEMM_SMEM);

    prep_cb_kernel<<<N_E, 256>>>(w);
    prep_z_kernel<<<M_ROWS, 256>>>(z);
    zero_counts_kernel<<<(N_E + 255) / 256, 256>>>();

    dim3 grid(N_E / BN, M_ROWS / BM);      // (64, 64)
    mma_gemm_kernel<<<grid, 256, GEMM_SMEM>>>(out);

    softmax_kernel<<<M_ROWS, 256>>>(out);

    cudaMemsetAsync(out + OFF_MINE, 0, (size_t)M_ROWS * N_E * sizeof(float));
    onehot_kernel<<<(M_ROWS + 255) / 256, 256>>>(out);

    zq_kernel<<<M_ROWS, 128>>>(z, out);
    finalize_kernel<<<1, 256>>>(out);
}

// round 4
// speedup vs baseline: 4.0812x; 1.1574x over previous
#include <cuda_runtime.h>
#include <cuda_bf16.h>
#include <math.h>
#include <stdint.h>

// Problem constants
#define M_ROWS 8192      // B*H*W
#define N_E    8192
#define E_DIM  512

// Output layout (flattened tuple, fp32)
#define OFF_PROB ((size_t)3)
#define OFF_D    (OFF_PROB + (size_t)M_ROWS * N_E)
#define OFF_ZQ   (OFF_D    + (size_t)M_ROWS * N_E)
#define OFF_PERP (OFF_ZQ   + (size_t)M_ROWS * E_DIM)
#define OFF_MINE (OFF_PERP + 1)
#define OFF_IDX  (OFF_MINE + (size_t)M_ROWS * N_E)

// ---------------------------------------------------------------------------
// Device scratch (no dynamic allocation allowed)
// ---------------------------------------------------------------------------
static __device__ float g_cb[(size_t)N_E * E_DIM];
static __device__ float g_cbnorm[N_E];
static __device__ float g_znorm[M_ROWS];
static __device__ int   g_idx[M_ROWS];
static __device__ int   g_counts[N_E];
static __device__ float g_cos[M_ROWS];
// bf16 hi/lo splits for tensor-core GEMM
static __device__ __align__(16) __nv_bfloat16 g_zhi[(size_t)M_ROWS * E_DIM];
static __device__ __align__(16) __nv_bfloat16 g_zlo[(size_t)M_ROWS * E_DIM];
static __device__ __align__(16) __nv_bfloat16 g_bhi[(size_t)N_E   * E_DIM];
static __device__ __align__(16) __nv_bfloat16 g_blo[(size_t)N_E   * E_DIM];

// ---------------------------------------------------------------------------
// PTX helpers (base ISA only: mma.sync / ldmatrix / cp.async)
// ---------------------------------------------------------------------------
__device__ __forceinline__ uint32_t smem_u32(const void* p) {
    uint32_t a;
    asm("{ .reg .u64 t; cvta.to.shared.u64 t, %1; cvt.u32.u64 %0, t; }"
        : "=r"(a) : "l"(p));
    return a;
}
__device__ __forceinline__ void cp16(uint32_t saddr, const void* g) {
    asm volatile("cp.async.cg.shared.global [%0], [%1], 16;"
                 :: "r"(saddr), "l"(g) : "memory");
}
__device__ __forceinline__ void ldsm4(uint32_t* r, uint32_t addr) {
    asm volatile("ldmatrix.sync.aligned.m8n8.x4.shared.b16 {%0,%1,%2,%3}, [%4];"
                 : "=r"(r[0]), "=r"(r[1]), "=r"(r[2]), "=r"(r[3]) : "r"(addr));
}
__device__ __forceinline__ void mma_bf16(float* c, const uint32_t* a, const uint32_t* b) {
    asm volatile(
        "mma.sync.aligned.m16n8k16.row.col.f32.bf16.bf16.f32 "
        "{%0,%1,%2,%3}, {%4,%5,%6,%7}, {%8,%9}, {%0,%1,%2,%3};"
        : "+f"(c[0]), "+f"(c[1]), "+f"(c[2]), "+f"(c[3])
        : "r"(a[0]), "r"(a[1]), "r"(a[2]), "r"(a[3]), "r"(b[0]), "r"(b[1]));
}

// ---------------------------------------------------------------------------
// Codebook prep: cb = w/||w||, cb_norm = ||cb||, bf16 hi/lo split
// ---------------------------------------------------------------------------
__global__ __launch_bounds__(256) void prep_cb_kernel(const float* __restrict__ w) {
    int r = blockIdx.x;
    int t = threadIdx.x;
    const float* row = w + (size_t)r * E_DIM;
    float v0 = row[t];
    float v1 = row[t + 256];

    __shared__ float sm[256];
    sm[t] = v0 * v0 + v1 * v1;
    __syncthreads();
    #pragma unroll
    for (int s = 128; s > 0; s >>= 1) {
        if (t < s) sm[t] += sm[t + s];
        __syncthreads();
    }
    float norm = sqrtf(sm[0]);
    __syncthreads();

    float c0 = v0 / norm;
    float c1 = v1 / norm;
    size_t base = (size_t)r * E_DIM;
    g_cb[base + t]       = c0;
    g_cb[base + t + 256] = c1;

    __nv_bfloat16 h0 = __float2bfloat16(c0);
    __nv_bfloat16 h1 = __float2bfloat16(c1);
    g_bhi[base + t]       = h0;
    g_bhi[base + t + 256] = h1;
    g_blo[base + t]       = __float2bfloat16(c0 - __bfloat162float(h0));
    g_blo[base + t + 256] = __float2bfloat16(c1 - __bfloat162float(h1));

    sm[t] = c0 * c0 + c1 * c1;
    __syncthreads();
    #pragma unroll
    for (int s = 128; s > 0; s >>= 1) {
        if (t < s) sm[t] += sm[t + s];
        __syncthreads();
    }
    if (t == 0) g_cbnorm[r] = sqrtf(sm[0]);
}

// ---------------------------------------------------------------------------
// z prep: row norms + bf16 hi/lo split
// ---------------------------------------------------------------------------
__global__ __launch_bounds__(256) void prep_z_kernel(const float* __restrict__ z) {
    int r = blockIdx.x;
    int t = threadIdx.x;
    const float* row = z + (size_t)r * E_DIM;
    float v0 = row[t];
    float v1 = row[t + 256];

    size_t base = (size_t)r * E_DIM;
    __nv_bfloat16 h0 = __float2bfloat16(v0);
    __nv_bfloat16 h1 = __float2bfloat16(v1);
    g_zhi[base + t]       = h0;
    g_zhi[base + t + 256] = h1;
    g_zlo[base + t]       = __float2bfloat16(v0 - __bfloat162float(h0));
    g_zlo[base + t + 256] = __float2bfloat16(v1 - __bfloat162float(h1));

    __shared__ float sm[256];
    sm[t] = v0 * v0 + v1 * v1;
    __syncthreads();
    #pragma unroll
    for (int s = 128; s > 0; s >>= 1) {
        if (t < s) sm[t] += sm[t + s];
        __syncthreads();
    }
    if (t == 0) g_znorm[r] = sqrtf(sm[0]);
}

__global__ void zero_counts_kernel() {
    int i = blockIdx.x * 256 + threadIdx.x;
    if (i < N_E) g_counts[i] = 0;
}

// ---------------------------------------------------------------------------
// mma.sync GEMM (3-term bf16 split: hi*hi + lo*hi + hi*lo):
// tile 128x128, K chunks of 64, cp.async double buffer with ONE barrier per
// chunk (load(c+1) overlaps compute(c)), 8 warps (4x2), warp tile 32x64.
// ---------------------------------------------------------------------------
#define BM 128
#define BN 128
#define KC 64
#define NCHUNK (E_DIM / KC)        // 8
#define STRIDE 144                 // bytes per 64-bf16 row (128 + 16 pad)
#define ARR_SZ (128 * STRIDE)      // 18432
#define STAGE_SZ (4 * ARR_SZ)      // 73728
#define GEMM_SMEM (2 * STAGE_SZ)   // 147456

__global__ __launch_bounds__(256, 1) void mma_gemm_kernel(float* __restrict__ out) {
    extern __shared__ char smem[];
    const uint32_t sbase = smem_u32(smem);
    const int tid = threadIdx.x;
    const int lane = tid & 31;
    const int wid = tid >> 5;
    const int wm = wid & 3;        // m-quadrant: 32 rows each
    const int wn = wid >> 2;       // n-half: 64 cols each
    const int r0 = blockIdx.y * BM;
    const int c0 = blockIdx.x * BN;

    float acc[2][8][4];
    #pragma unroll
    for (int a = 0; a < 2; a++)
        #pragma unroll
        for (int b = 0; b < 8; b++)
            #pragma unroll
            for (int e = 0; e < 4; e++) acc[a][b][e] = 0.0f;

    // ---- chunk loader (cp.async), all 256 threads ----
    auto load_chunk = [&](int c, int stage) {
        uint32_t sb = sbase + (uint32_t)stage * STAGE_SZ;
        #pragma unroll
        for (int i = 0; i < 4; i++) {
            int slot = tid + i * 256;      // 0..1023
            int row = slot >> 3;
            int u   = slot & 7;
            uint32_t so = (uint32_t)row * STRIDE + (uint32_t)u * 16;
            size_t ga = (size_t)(r0 + row) * E_DIM + c * KC + u * 8;
            size_t gb = (size_t)(c0 + row) * E_DIM + c * KC + u * 8;
            cp16(sb + so,              g_zhi + ga);
            cp16(sb + ARR_SZ + so,     g_zlo + ga);
            cp16(sb + 2 * ARR_SZ + so, g_bhi + gb);
            cp16(sb + 3 * ARR_SZ + so, g_blo + gb);
        }
        asm volatile("cp.async.commit_group;" ::: "memory");
    };

    // per-lane ldmatrix address components
    const uint32_t aRow  = (uint32_t)(wm * 32 + (lane & 15)) * STRIDE + ((lane >> 4) * 16);
    const uint32_t bRow  = (uint32_t)(wn * 64 + (lane & 7) + ((lane >> 4) << 3)) * STRIDE
                         + (((lane >> 3) & 1) * 16);

    auto compute = [&](int stage) {
        uint32_t sb = sbase + (uint32_t)stage * STAGE_SZ;
        uint32_t aHi = sb + aRow;
        uint32_t aLo = aHi + ARR_SZ;
        uint32_t bHi = sb + 2 * ARR_SZ + bRow;
        uint32_t bLo = bHi + ARR_SZ;
        #pragma unroll
        for (int ks = 0; ks < 4; ks++) {
            uint32_t ah[2][4], al[2][4];
            ldsm4(ah[0], aHi + ks * 32);
            ldsm4(ah[1], aHi + 16 * STRIDE + ks * 32);
            ldsm4(al[0], aLo + ks * 32);
            ldsm4(al[1], aLo + 16 * STRIDE + ks * 32);
            #pragma unroll
            for (int np = 0; np < 4; np++) {
                uint32_t bh[4], bl[4];
                ldsm4(bh, bHi + np * 16 * STRIDE + ks * 32);
                ldsm4(bl, bLo + np * 16 * STRIDE + ks * 32);
                #pragma unroll
                for (int mt = 0; mt < 2; mt++) {
                    #pragma unroll
                    for (int s = 0; s < 2; s++) {
                        float* a4 = acc[mt][np * 2 + s];
                        mma_bf16(a4, ah[mt], bh + 2 * s);   // hi*hi
                        mma_bf16(a4, al[mt], bh + 2 * s);   // lo*hi
                        mma_bf16(a4, ah[mt], bl + 2 * s);   // hi*lo
                    }
                }
            }
        }
    };

    // ---- pipelined mainloop: one barrier per chunk ----
    load_chunk(0, 0);
    #pragma unroll 1
    for (int c = 0; c < NCHUNK; c++) {
        asm volatile("cp.async.wait_group 0;" ::: "memory");   // chunk c landed
        __syncthreads();       // all warps done with compute(c-1) -> stage reusable
        if (c + 1 < NCHUNK) load_chunk(c + 1, (c + 1) & 1);    // overlaps compute(c)
        compute(c & 1);
    }

    // ---- epilogue: scale + scalar stores (OFF_D only 4B-aligned) ----
    float* D = out + OFF_D;
    const int gr = lane >> 2;
    const int gc = (lane & 3) * 2;
    #pragma unroll
    for (int mt = 0; mt < 2; mt++) {
        int rA = r0 + wm * 32 + mt * 16 + gr;
        int rB = rA + 8;
        float znA = g_znorm[rA];
        float znB = g_znorm[rB];
        #pragma unroll
        for (int n8 = 0; n8 < 8; n8++) {
            int cc = c0 + wn * 64 + n8 * 8 + gc;
            float cn0 = g_cbnorm[cc];
            float cn1 = g_cbnorm[cc + 1];
            float* a4 = acc[mt][n8];
            D[(size_t)rA * N_E + cc]     = a4[0] / (znA * cn0 + 1e-6f);
            D[(size_t)rA * N_E + cc + 1] = a4[1] / (znA * cn1 + 1e-6f);
            D[(size_t)rB * N_E + cc]     = a4[2] / (znB * cn0 + 1e-6f);
            D[(size_t)rB * N_E + cc + 1] = a4[3] / (znB * cn1 + 1e-6f);
        }
    }
}

// ---------------------------------------------------------------------------
// Polynomial exp on [-1,1] (degree-10 Taylor, FMA pipe; avoids MUFU wall)
// ---------------------------------------------------------------------------
__device__ __forceinline__ float exp_poly(float x) {
    const float c10 = 2.7557319e-7f, c9 = 2.7557319e-6f, c8 = 2.4801587e-5f;
    const float c7 = 1.9841270e-4f,  c6 = 1.3888889e-3f, c5 = 8.3333333e-3f;
    const float c4 = 4.1666668e-2f,  c3 = 1.6666667e-1f, c2 = 0.5f;
    float p = c10;
    p = fmaf(p, x, c9);
    p = fmaf(p, x, c8);
    p = fmaf(p, x, c7);
    p = fmaf(p, x, c6);
    p = fmaf(p, x, c5);
    p = fmaf(p, x, c4);
    p = fmaf(p, x, c3);
    p = fmaf(p, x, c2);
    p = fmaf(p, x, 1.0f);
    p = fmaf(p, x, 1.0f);
    return p;
}

// ---------------------------------------------------------------------------
// Fused per-row: argmax (first-index tie-break), histogram, idx output,
// softmax (poly exp, shift-free: d in [-1,1]), AND min_encodings one-hot row
// (zeros + single 1.0) — replaces separate memset + onehot passes.
// ---------------------------------------------------------------------------
__global__ __launch_bounds__(256) void softmax_kernel(float* __restrict__ out) {
    __shared__ float sred[256];
    __shared__ int   sidx[256];

    int r = blockIdx.x;
    int t = threadIdx.x;
    const float* drow = out + OFF_D + (size_t)r * N_E;

    float e[32];
    float best = -2.0f;
    int bi = 0;
    float sum = 0.0f;
    #pragma unroll
    for (int j = 0; j < 32; j++) {
        int i = t + j * 256;
        float v = drow[i];
        if (v > best) { best = v; bi = i; }   // j ascending => first index kept
        float ev = exp_poly(v);
        e[j] = ev;
        sum += ev;
    }
    sred[t] = best; sidx[t] = bi;
    __syncthreads();
    for (int s = 128; s > 0; s >>= 1) {
        if (t < s) {
            float v = sred[t + s]; int ii = sidx[t + s];
            if (v > sred[t] || (v == sred[t] && ii < sidx[t])) {
                sred[t] = v; sidx[t] = ii;
            }
        }
        __syncthreads();
    }
    if (t == 0) {
        int idx = sidx[0];
        g_idx[r] = idx;
        atomicAdd(&g_counts[idx], 1);
        out[OFF_IDX + r] = (float)idx;
    }
    __syncthreads();

    sred[t] = sum;
    __syncthreads();
    for (int s = 128; s > 0; s >>= 1) {
        if (t < s) sred[t] += sred[t + s];
        __syncthreads();
    }
    float inv = 1.0f / sred[0];

    float* prow = out + OFF_PROB + (size_t)r * N_E;
    float* mrow = out + OFF_MINE + (size_t)r * N_E;
    #pragma unroll
    for (int j = 0; j < 32; j++) {
        int i = t + j * 256;
        prow[i] = e[j] * inv;
        mrow[i] = 0.0f;
    }
    __syncthreads();
    if (t == 0) mrow[sidx[0]] = 1.0f;
}

// ---------------------------------------------------------------------------
__global__ __launch_bounds__(128) void zq_kernel(const float* __restrict__ Z,
                                                 float* __restrict__ out) {
    int r = blockIdx.x;
    int t = threadIdx.x;
    int j = g_idx[r];
    const float* zr = Z    + (size_t)r * E_DIM;
    const float* cr = g_cb + (size_t)j * E_DIM;
    float* o = out + OFF_ZQ + (size_t)r * E_DIM;

    float dot = 0.0f, nc = 0.0f, nz = 0.0f;
    #pragma unroll
    for (int i = t; i < E_DIM; i += 128) {
        float zv = zr[i];
        float cv = cr[i];
        o[i] = zv + (cv - zv);
        dot += zv * cv;
        nc  += cv * cv;
        nz  += zv * zv;
    }
    __shared__ float sd_[128], sc_[128], sz_[128];
    sd_[t] = dot; sc_[t] = nc; sz_[t] = nz;
    __syncthreads();
    for (int s = 64; s > 0; s >>= 1) {
        if (t < s) { sd_[t] += sd_[t + s]; sc_[t] += sc_[t + s]; sz_[t] += sz_[t + s]; }
        __syncthreads();
    }
    if (t == 0) {
        g_cos[r] = sd_[0] / (fmaxf(sqrtf(sc_[0]), 1e-8f) * fmaxf(sqrtf(sz_[0]), 1e-8f));
    }
}

// ---------------------------------------------------------------------------
__global__ __launch_bounds__(256) void finalize_kernel(float* __restrict__ out) {
    int t = threadIdx.x;
    __shared__ float s1[256], s2[256], s3[256];

    float kl = 0.0f, ent = 0.0f, cs = 0.0f;
    const float invM  = 1.0f / (float)M_ROWS;
    const float invNE = 1.0f / (float)N_E;
    for (int j = t; j < N_E; j += 256) {
        float em = (float)g_counts[j] * invM;
        kl  += em * logf(invNE / (em + 1e-6f));
        ent += em * logf(em + 1e-6f);
    }
    for (int j = t; j < M_ROWS; j += 256) cs += g_cos[j];

    s1[t] = kl; s2[t] = ent; s3[t] = cs;
    __syncthreads();
    for (int s = 128; s > 0; s >>= 1) {
        if (t < s) { s1[t] += s1[t + s]; s2[t] += s2[t + s]; s3[t] += s3[t + s]; }
        __syncthreads();
    }
    if (t == 0) {
        float mc = s3[0] * invM;
        out[0] = (1.0f - mc) + 0.25f * (1.0f - mc);
        out[1] = 0.0f;
        out[2] = -s1[0];
        out[OFF_PERP] = expf(-s2[0]);
    }
}

// ---------------------------------------------------------------------------
extern "C" void kernel_launch(void* const* d_in, const int* in_sizes, int n_in,
                              void* d_out, int out_size) {
    const float* z = (const float*)d_in[0];
    const float* w = (const float*)d_in[1];
    float* out = (float*)d_out;

    cudaFuncSetAttribute(mma_gemm_kernel,
                         cudaFuncAttributeMaxDynamicSharedMemorySize, GEMM_SMEM);

    prep_cb_kernel<<<N_E, 256>>>(w);
    prep_z_kernel<<<M_ROWS, 256>>>(z);
    zero_counts_kernel<<<(N_E + 255) / 256, 256>>>();

    dim3 grid(N_E / BN, M_ROWS / BM);      // (64, 64)
    mma_gemm_kernel<<<grid, 256, GEMM_SMEM>>>(out);

    softmax_kernel<<<M_ROWS, 256>>>(out);

    zq_kernel<<<M_ROWS, 128>>>(z, out);
    finalize_kernel<<<1, 256>>>(out);
}

// round 5
// speedup vs baseline: 4.4694x; 1.0951x over previous
#include <cuda_runtime.h>
#include <cuda_bf16.h>
#include <math.h>
#include <stdint.h>

// Problem constants
#define M_ROWS 8192      // B*H*W
#define N_E    8192
#define E_DIM  512

// Output layout (flattened tuple, fp32)
#define OFF_PROB ((size_t)3)
#define OFF_D    (OFF_PROB + (size_t)M_ROWS * N_E)
#define OFF_ZQ   (OFF_D    + (size_t)M_ROWS * N_E)
#define OFF_PERP (OFF_ZQ   + (size_t)M_ROWS * E_DIM)
#define OFF_MINE (OFF_PERP + 1)
#define OFF_IDX  (OFF_MINE + (size_t)M_ROWS * N_E)

// ---------------------------------------------------------------------------
// Device scratch (no dynamic allocation allowed)
// ---------------------------------------------------------------------------
static __device__ float g_cb[(size_t)N_E * E_DIM];
static __device__ float g_cbnorm[N_E];
static __device__ float g_znorm[M_ROWS];
static __device__ int   g_idx[M_ROWS];
static __device__ int   g_counts[N_E];
static __device__ float g_cos[M_ROWS];
// bf16 hi/lo splits for tensor-core GEMM
static __device__ __align__(16) __nv_bfloat16 g_zhi[(size_t)M_ROWS * E_DIM];
static __device__ __align__(16) __nv_bfloat16 g_zlo[(size_t)M_ROWS * E_DIM];
static __device__ __align__(16) __nv_bfloat16 g_bhi[(size_t)N_E   * E_DIM];
static __device__ __align__(16) __nv_bfloat16 g_blo[(size_t)N_E   * E_DIM];

// ---------------------------------------------------------------------------
// PTX helpers (base ISA only: mma.sync / ldmatrix / cp.async)
// ---------------------------------------------------------------------------
__device__ __forceinline__ uint32_t smem_u32(const void* p) {
    uint32_t a;
    asm("{ .reg .u64 t; cvta.to.shared.u64 t, %1; cvt.u32.u64 %0, t; }"
        : "=r"(a) : "l"(p));
    return a;
}
__device__ __forceinline__ void cp16(uint32_t saddr, const void* g) {
    asm volatile("cp.async.cg.shared.global [%0], [%1], 16;"
                 :: "r"(saddr), "l"(g) : "memory");
}
__device__ __forceinline__ void ldsm4(uint32_t* r, uint32_t addr) {
    asm volatile("ldmatrix.sync.aligned.m8n8.x4.shared.b16 {%0,%1,%2,%3}, [%4];"
                 : "=r"(r[0]), "=r"(r[1]), "=r"(r[2]), "=r"(r[3]) : "r"(addr));
}
__device__ __forceinline__ void mma_bf16(float* c, const uint32_t* a, const uint32_t* b) {
    asm volatile(
        "mma.sync.aligned.m16n8k16.row.col.f32.bf16.bf16.f32 "
        "{%0,%1,%2,%3}, {%4,%5,%6,%7}, {%8,%9}, {%0,%1,%2,%3};"
        : "+f"(c[0]), "+f"(c[1]), "+f"(c[2]), "+f"(c[3])
        : "r"(a[0]), "r"(a[1]), "r"(a[2]), "r"(a[3]), "r"(b[0]), "r"(b[1]));
}

// ---------------------------------------------------------------------------
// Codebook prep: cb = w/||w||, cb_norm = ||cb||, bf16 hi/lo split
// ---------------------------------------------------------------------------
__global__ __launch_bounds__(256) void prep_cb_kernel(const float* __restrict__ w) {
    int r = blockIdx.x;
    int t = threadIdx.x;
    const float* row = w + (size_t)r * E_DIM;
    float v0 = row[t];
    float v1 = row[t + 256];

    __shared__ float sm[256];
    sm[t] = v0 * v0 + v1 * v1;
    __syncthreads();
    #pragma unroll
    for (int s = 128; s > 0; s >>= 1) {
        if (t < s) sm[t] += sm[t + s];
        __syncthreads();
    }
    float norm = sqrtf(sm[0]);
    __syncthreads();

    float c0 = v0 / norm;
    float c1 = v1 / norm;
    size_t base = (size_t)r * E_DIM;
    g_cb[base + t]       = c0;
    g_cb[base + t + 256] = c1;

    __nv_bfloat16 h0 = __float2bfloat16(c0);
    __nv_bfloat16 h1 = __float2bfloat16(c1);
    g_bhi[base + t]       = h0;
    g_bhi[base + t + 256] = h1;
    g_blo[base + t]       = __float2bfloat16(c0 - __bfloat162float(h0));
    g_blo[base + t + 256] = __float2bfloat16(c1 - __bfloat162float(h1));

    sm[t] = c0 * c0 + c1 * c1;
    __syncthreads();
    #pragma unroll
    for (int s = 128; s > 0; s >>= 1) {
        if (t < s) sm[t] += sm[t + s];
        __syncthreads();
    }
    if (t == 0) g_cbnorm[r] = sqrtf(sm[0]);
}

// ---------------------------------------------------------------------------
// z prep: row norms + bf16 hi/lo split
// ---------------------------------------------------------------------------
__global__ __launch_bounds__(256) void prep_z_kernel(const float* __restrict__ z) {
    int r = blockIdx.x;
    int t = threadIdx.x;
    const float* row = z + (size_t)r * E_DIM;
    float v0 = row[t];
    float v1 = row[t + 256];

    size_t base = (size_t)r * E_DIM;
    __nv_bfloat16 h0 = __float2bfloat16(v0);
    __nv_bfloat16 h1 = __float2bfloat16(v1);
    g_zhi[base + t]       = h0;
    g_zhi[base + t + 256] = h1;
    g_zlo[base + t]       = __float2bfloat16(v0 - __bfloat162float(h0));
    g_zlo[base + t + 256] = __float2bfloat16(v1 - __bfloat162float(h1));

    __shared__ float sm[256];
    sm[t] = v0 * v0 + v1 * v1;
    __syncthreads();
    #pragma unroll
    for (int s = 128; s > 0; s >>= 1) {
        if (t < s) sm[t] += sm[t + s];
        __syncthreads();
    }
    if (t == 0) g_znorm[r] = sqrtf(sm[0]);
}

__global__ void zero_counts_kernel() {
    int i = blockIdx.x * 256 + threadIdx.x;
    if (i < N_E) g_counts[i] = 0;
}

// ---------------------------------------------------------------------------
// mma.sync GEMM (3-term bf16 split): tile 128x128, K chunks of 32,
// cp.async double buffer, one barrier per chunk, 8 warps (4x2),
// warp tile 32x64. smem 80KB/CTA -> 2 CTAs per SM for latency overlap.
// ---------------------------------------------------------------------------
#define BM 128
#define BN 128
#define KC 32
#define NCHUNK (E_DIM / KC)        // 16
#define STRIDE 80                  // bytes per 32-bf16 row (64 + 16 pad)
#define ARR_SZ (128 * STRIDE)      // 10240
#define STAGE_SZ (4 * ARR_SZ)      // 40960
#define GEMM_SMEM (2 * STAGE_SZ)   // 81920

__global__ __launch_bounds__(256, 2) void mma_gemm_kernel(float* __restrict__ out) {
    extern __shared__ char smem[];
    const uint32_t sbase = smem_u32(smem);
    const int tid = threadIdx.x;
    const int lane = tid & 31;
    const int wid = tid >> 5;
    const int wm = wid & 3;        // m-quadrant: 32 rows each
    const int wn = wid >> 2;       // n-half: 64 cols each
    const int r0 = blockIdx.y * BM;
    const int c0 = blockIdx.x * BN;

    float acc[2][8][4];
    #pragma unroll
    for (int a = 0; a < 2; a++)
        #pragma unroll
        for (int b = 0; b < 8; b++)
            #pragma unroll
            for (int e = 0; e < 4; e++) acc[a][b][e] = 0.0f;

    // ---- chunk loader (cp.async): 4 arrays x 128 rows x 4 uint4 ----
    auto load_chunk = [&](int c, int stage) {
        uint32_t sb = sbase + (uint32_t)stage * STAGE_SZ;
        #pragma unroll
        for (int i = 0; i < 2; i++) {
            int slot = tid + i * 256;      // 0..511
            int row = slot >> 2;
            int u   = slot & 3;
            uint32_t so = (uint32_t)row * STRIDE + (uint32_t)u * 16;
            size_t ga = (size_t)(r0 + row) * E_DIM + c * KC + u * 8;
            size_t gb = (size_t)(c0 + row) * E_DIM + c * KC + u * 8;
            cp16(sb + so,              g_zhi + ga);
            cp16(sb + ARR_SZ + so,     g_zlo + ga);
            cp16(sb + 2 * ARR_SZ + so, g_bhi + gb);
            cp16(sb + 3 * ARR_SZ + so, g_blo + gb);
        }
        asm volatile("cp.async.commit_group;" ::: "memory");
    };

    // per-lane ldmatrix address components
    const uint32_t aRow  = (uint32_t)(wm * 32 + (lane & 15)) * STRIDE + ((lane >> 4) * 16);
    const uint32_t bRow  = (uint32_t)(wn * 64 + (lane & 7) + ((lane >> 4) << 3)) * STRIDE
                         + (((lane >> 3) & 1) * 16);

    auto compute = [&](int stage) {
        uint32_t sb = sbase + (uint32_t)stage * STAGE_SZ;
        uint32_t aHi = sb + aRow;
        uint32_t aLo = aHi + ARR_SZ;
        uint32_t bHi = sb + 2 * ARR_SZ + bRow;
        uint32_t bLo = bHi + ARR_SZ;
        #pragma unroll
        for (int ks = 0; ks < 2; ks++) {
            uint32_t ah[2][4], al[2][4];
            ldsm4(ah[0], aHi + ks * 32);
            ldsm4(ah[1], aHi + 16 * STRIDE + ks * 32);
            ldsm4(al[0], aLo + ks * 32);
            ldsm4(al[1], aLo + 16 * STRIDE + ks * 32);
            #pragma unroll
            for (int np = 0; np < 4; np++) {
                uint32_t bh[4], bl[4];
                ldsm4(bh, bHi + np * 16 * STRIDE + ks * 32);
                ldsm4(bl, bLo + np * 16 * STRIDE + ks * 32);
                #pragma unroll
                for (int mt = 0; mt < 2; mt++) {
                    #pragma unroll
                    for (int s = 0; s < 2; s++) {
                        float* a4 = acc[mt][np * 2 + s];
                        mma_bf16(a4, ah[mt], bh + 2 * s);   // hi*hi
                        mma_bf16(a4, al[mt], bh + 2 * s);   // lo*hi
                        mma_bf16(a4, ah[mt], bl + 2 * s);   // hi*lo
                    }
                }
            }
        }
    };

    // ---- pipelined mainloop: one barrier per chunk ----
    load_chunk(0, 0);
    #pragma unroll 1
    for (int c = 0; c < NCHUNK; c++) {
        asm volatile("cp.async.wait_group 0;" ::: "memory");   // chunk c landed
        __syncthreads();       // all warps done with compute(c-1) -> stage reusable
        if (c + 1 < NCHUNK) load_chunk(c + 1, (c + 1) & 1);    // overlaps compute(c)
        compute(c & 1);
    }

    // ---- epilogue: scale + scalar stores (OFF_D only 4B-aligned) ----
    float* D = out + OFF_D;
    const int gr = lane >> 2;
    const int gc = (lane & 3) * 2;
    #pragma unroll
    for (int mt = 0; mt < 2; mt++) {
        int rA = r0 + wm * 32 + mt * 16 + gr;
        int rB = rA + 8;
        float znA = g_znorm[rA];
        float znB = g_znorm[rB];
        #pragma unroll
        for (int n8 = 0; n8 < 8; n8++) {
            int cc = c0 + wn * 64 + n8 * 8 + gc;
            float cn0 = g_cbnorm[cc];
            float cn1 = g_cbnorm[cc + 1];
            float* a4 = acc[mt][n8];
            D[(size_t)rA * N_E + cc]     = a4[0] / (znA * cn0 + 1e-6f);
            D[(size_t)rA * N_E + cc + 1] = a4[1] / (znA * cn1 + 1e-6f);
            D[(size_t)rB * N_E + cc]     = a4[2] / (znB * cn0 + 1e-6f);
            D[(size_t)rB * N_E + cc + 1] = a4[3] / (znB * cn1 + 1e-6f);
        }
    }
}

// ---------------------------------------------------------------------------
// Polynomial exp on [-1,1] (degree-10 Taylor, FMA pipe; avoids MUFU wall)
// ---------------------------------------------------------------------------
__device__ __forceinline__ float exp_poly(float x) {
    const float c10 = 2.7557319e-7f, c9 = 2.7557319e-6f, c8 = 2.4801587e-5f;
    const float c7 = 1.9841270e-4f,  c6 = 1.3888889e-3f, c5 = 8.3333333e-3f;
    const float c4 = 4.1666668e-2f,  c3 = 1.6666667e-1f, c2 = 0.5f;
    float p = c10;
    p = fmaf(p, x, c9);
    p = fmaf(p, x, c8);
    p = fmaf(p, x, c7);
    p = fmaf(p, x, c6);
    p = fmaf(p, x, c5);
    p = fmaf(p, x, c4);
    p = fmaf(p, x, c3);
    p = fmaf(p, x, c2);
    p = fmaf(p, x, 1.0f);
    p = fmaf(p, x, 1.0f);
    return p;
}

// ---------------------------------------------------------------------------
// Fused per-row: argmax (first-index tie-break), histogram, idx output,
// softmax (poly exp, shift-free: d in [-1,1]), AND min_encodings one-hot row.
// ---------------------------------------------------------------------------
__global__ __launch_bounds__(256) void softmax_kernel(float* __restrict__ out) {
    __shared__ float sred[256];
    __shared__ int   sidx[256];

    int r = blockIdx.x;
    int t = threadIdx.x;
    const float* drow = out + OFF_D + (size_t)r * N_E;

    float e[32];
    float best = -2.0f;
    int bi = 0;
    float sum = 0.0f;
    #pragma unroll
    for (int j = 0; j < 32; j++) {
        int i = t + j * 256;
        float v = drow[i];
        if (v > best) { best = v; bi = i; }   // j ascending => first index kept
        float ev = exp_poly(v);
        e[j] = ev;
        sum += ev;
    }
    sred[t] = best; sidx[t] = bi;
    __syncthreads();
    for (int s = 128; s > 0; s >>= 1) {
        if (t < s) {
            float v = sred[t + s]; int ii = sidx[t + s];
            if (v > sred[t] || (v == sred[t] && ii < sidx[t])) {
                sred[t] = v; sidx[t] = ii;
            }
        }
        __syncthreads();
    }
    if (t == 0) {
        int idx = sidx[0];
        g_idx[r] = idx;
        atomicAdd(&g_counts[idx], 1);
        out[OFF_IDX + r] = (float)idx;
    }
    __syncthreads();

    sred[t] = sum;
    __syncthreads();
    for (int s = 128; s > 0; s >>= 1) {
        if (t < s) sred[t] += sred[t + s];
        __syncthreads();
    }
    float inv = 1.0f / sred[0];

    float* prow = out + OFF_PROB + (size_t)r * N_E;
    float* mrow = out + OFF_MINE + (size_t)r * N_E;
    #pragma unroll
    for (int j = 0; j < 32; j++) {
        int i = t + j * 256;
        prow[i] = e[j] * inv;
        mrow[i] = 0.0f;
    }
    __syncthreads();
    if (t == 0) mrow[sidx[0]] = 1.0f;
}

// ---------------------------------------------------------------------------
__global__ __launch_bounds__(128) void zq_kernel(const float* __restrict__ Z,
                                                 float* __restrict__ out) {
    int r = blockIdx.x;
    int t = threadIdx.x;
    int j = g_idx[r];
    const float* zr = Z    + (size_t)r * E_DIM;
    const float* cr = g_cb + (size_t)j * E_DIM;
    float* o = out + OFF_ZQ + (size_t)r * E_DIM;

    float dot = 0.0f, nc = 0.0f, nz = 0.0f;
    #pragma unroll
    for (int i = t; i < E_DIM; i += 128) {
        float zv = zr[i];
        float cv = cr[i];
        o[i] = zv + (cv - zv);
        dot += zv * cv;
        nc  += cv * cv;
        nz  += zv * zv;
    }
    __shared__ float sd_[128], sc_[128], sz_[128];
    sd_[t] = dot; sc_[t] = nc; sz_[t] = nz;
    __syncthreads();
    for (int s = 64; s > 0; s >>= 1) {
        if (t < s) { sd_[t] += sd_[t + s]; sc_[t] += sc_[t + s]; sz_[t] += sz_[t + s]; }
        __syncthreads();
    }
    if (t == 0) {
        g_cos[r] = sd_[0] / (fmaxf(sqrtf(sc_[0]), 1e-8f) * fmaxf(sqrtf(sz_[0]), 1e-8f));
    }
}

// ---------------------------------------------------------------------------
__global__ __launch_bounds__(256) void finalize_kernel(float* __restrict__ out) {
    int t = threadIdx.x;
    __shared__ float s1[256], s2[256], s3[256];

    float kl = 0.0f, ent = 0.0f, cs = 0.0f;
    const float invM  = 1.0f / (float)M_ROWS;
    const float invNE = 1.0f / (float)N_E;
    for (int j = t; j < N_E; j += 256) {
        float em = (float)g_counts[j] * invM;
        kl  += em * logf(invNE / (em + 1e-6f));
        ent += em * logf(em + 1e-6f);
    }
    for (int j = t; j < M_ROWS; j += 256) cs += g_cos[j];

    s1[t] = kl; s2[t] = ent; s3[t] = cs;
    __syncthreads();
    for (int s = 128; s > 0; s >>= 1) {
        if (t < s) { s1[t] += s1[t + s]; s2[t] += s2[t + s]; s3[t] += s3[t + s]; }
        __syncthreads();
    }
    if (t == 0) {
        float mc = s3[0] * invM;
        out[0] = (1.0f - mc) + 0.25f * (1.0f - mc);
        out[1] = 0.0f;
        out[2] = -s1[0];
        out[OFF_PERP] = expf(-s2[0]);
    }
}

// ---------------------------------------------------------------------------
extern "C" void kernel_launch(void* const* d_in, const int* in_sizes, int n_in,
                              void* d_out, int out_size) {
    const float* z = (const float*)d_in[0];
    const float* w = (const float*)d_in[1];
    float* out = (float*)d_out;

    cudaFuncSetAttribute(mma_gemm_kernel,
                         cudaFuncAttributeMaxDynamicSharedMemorySize, GEMM_SMEM);

    prep_cb_kernel<<<N_E, 256>>>(w);
    prep_z_kernel<<<M_ROWS, 256>>>(z);
    zero_counts_kernel<<<(N_E + 255) / 256, 256>>>();

    dim3 grid(N_E / BN, M_ROWS / BM);      // (64, 64)
    mma_gemm_kernel<<<grid, 256, GEMM_SMEM>>>(out);

    softmax_kernel<<<M_ROWS, 256>>>(out);

    zq_kernel<<<M_ROWS, 128>>>(z, out);
    finalize_kernel<<<1, 256>>>(out);
}

// round 6
// speedup vs baseline: 4.4881x; 1.0042x over previous
#include <cuda_runtime.h>
#include <cuda_bf16.h>
#include <math.h>
#include <stdint.h>

// Problem constants
#define M_ROWS 8192      // B*H*W
#define N_E    8192
#define E_DIM  512

// Output layout (flattened tuple, fp32)
#define OFF_PROB ((size_t)3)
#define OFF_D    (OFF_PROB + (size_t)M_ROWS * N_E)
#define OFF_ZQ   (OFF_D    + (size_t)M_ROWS * N_E)
#define OFF_PERP (OFF_ZQ   + (size_t)M_ROWS * E_DIM)
#define OFF_MINE (OFF_PERP + 1)
#define OFF_IDX  (OFF_MINE + (size_t)M_ROWS * N_E)

// ---------------------------------------------------------------------------
// Device scratch (no dynamic allocation allowed)
// ---------------------------------------------------------------------------
static __device__ float g_cb[(size_t)N_E * E_DIM];
static __device__ float g_cbnorm[N_E];
static __device__ float g_znorm[M_ROWS];
static __device__ int   g_idx[M_ROWS];
static __device__ int   g_counts[N_E];
static __device__ float g_cos[M_ROWS];
// bf16 hi/lo splits for tensor-core GEMM
static __device__ __align__(16) __nv_bfloat16 g_zhi[(size_t)M_ROWS * E_DIM];
static __device__ __align__(16) __nv_bfloat16 g_zlo[(size_t)M_ROWS * E_DIM];
static __device__ __align__(16) __nv_bfloat16 g_bhi[(size_t)N_E   * E_DIM];
static __device__ __align__(16) __nv_bfloat16 g_blo[(size_t)N_E   * E_DIM];

// ---------------------------------------------------------------------------
// PTX helpers (base ISA only: mma.sync / ldmatrix / cp.async)
// ---------------------------------------------------------------------------
__device__ __forceinline__ uint32_t smem_u32(const void* p) {
    uint32_t a;
    asm("{ .reg .u64 t; cvta.to.shared.u64 t, %1; cvt.u32.u64 %0, t; }"
        : "=r"(a) : "l"(p));
    return a;
}
__device__ __forceinline__ void cp16(uint32_t saddr, const void* g) {
    asm volatile("cp.async.cg.shared.global [%0], [%1], 16;"
                 :: "r"(saddr), "l"(g) : "memory");
}
__device__ __forceinline__ void ldsm4(uint32_t* r, uint32_t addr) {
    asm volatile("ldmatrix.sync.aligned.m8n8.x4.shared.b16 {%0,%1,%2,%3}, [%4];"
                 : "=r"(r[0]), "=r"(r[1]), "=r"(r[2]), "=r"(r[3]) : "r"(addr));
}
__device__ __forceinline__ void mma_bf16(float* c, const uint32_t* a, const uint32_t* b) {
    asm volatile(
        "mma.sync.aligned.m16n8k16.row.col.f32.bf16.bf16.f32 "
        "{%0,%1,%2,%3}, {%4,%5,%6,%7}, {%8,%9}, {%0,%1,%2,%3};"
        : "+f"(c[0]), "+f"(c[1]), "+f"(c[2]), "+f"(c[3])
        : "r"(a[0]), "r"(a[1]), "r"(a[2]), "r"(a[3]), "r"(b[0]), "r"(b[1]));
}

// ---------------------------------------------------------------------------
// Codebook prep: cb = w/||w||, cb_norm = ||cb||, bf16 hi/lo split
// ---------------------------------------------------------------------------
__global__ __launch_bounds__(256) void prep_cb_kernel(const float* __restrict__ w) {
    int r = blockIdx.x;
    int t = threadIdx.x;
    const float* row = w + (size_t)r * E_DIM;
    float v0 = row[t];
    float v1 = row[t + 256];

    __shared__ float sm[256];
    sm[t] = v0 * v0 + v1 * v1;
    __syncthreads();
    #pragma unroll
    for (int s = 128; s > 0; s >>= 1) {
        if (t < s) sm[t] += sm[t + s];
        __syncthreads();
    }
    float norm = sqrtf(sm[0]);
    __syncthreads();

    float c0 = v0 / norm;
    float c1 = v1 / norm;
    size_t base = (size_t)r * E_DIM;
    g_cb[base + t]       = c0;
    g_cb[base + t + 256] = c1;

    __nv_bfloat16 h0 = __float2bfloat16(c0);
    __nv_bfloat16 h1 = __float2bfloat16(c1);
    g_bhi[base + t]       = h0;
    g_bhi[base + t + 256] = h1;
    g_blo[base + t]       = __float2bfloat16(c0 - __bfloat162float(h0));
    g_blo[base + t + 256] = __float2bfloat16(c1 - __bfloat162float(h1));

    sm[t] = c0 * c0 + c1 * c1;
    __syncthreads();
    #pragma unroll
    for (int s = 128; s > 0; s >>= 1) {
        if (t < s) sm[t] += sm[t + s];
        __syncthreads();
    }
    if (t == 0) g_cbnorm[r] = sqrtf(sm[0]);
}

// ---------------------------------------------------------------------------
// z prep: row norms + bf16 hi/lo split
// ---------------------------------------------------------------------------
__global__ __launch_bounds__(256) void prep_z_kernel(const float* __restrict__ z) {
    int r = blockIdx.x;
    int t = threadIdx.x;
    const float* row = z + (size_t)r * E_DIM;
    float v0 = row[t];
    float v1 = row[t + 256];

    size_t base = (size_t)r * E_DIM;
    __nv_bfloat16 h0 = __float2bfloat16(v0);
    __nv_bfloat16 h1 = __float2bfloat16(v1);
    g_zhi[base + t]       = h0;
    g_zhi[base + t + 256] = h1;
    g_zlo[base + t]       = __float2bfloat16(v0 - __bfloat162float(h0));
    g_zlo[base + t + 256] = __float2bfloat16(v1 - __bfloat162float(h1));

    __shared__ float sm[256];
    sm[t] = v0 * v0 + v1 * v1;
    __syncthreads();
    #pragma unroll
    for (int s = 128; s > 0; s >>= 1) {
        if (t < s) sm[t] += sm[t + s];
        __syncthreads();
    }
    if (t == 0) g_znorm[r] = sqrtf(sm[0]);
}

__global__ void zero_counts_kernel() {
    int i = blockIdx.x * 256 + threadIdx.x;
    if (i < N_E) g_counts[i] = 0;
}

// ---------------------------------------------------------------------------
// mma.sync GEMM (3-term bf16 split): tile 128x128, K chunks of 32,
// cp.async double buffer, one barrier per chunk, 8 warps (4x2),
// warp tile 32x64. 80KB smem/CTA -> 2 CTAs/SM.
// Inner loop: term-major MMA order (acc RAW distance 4) + explicit
// B-fragment double buffering to hide LDS latency.
// ---------------------------------------------------------------------------
#define BM 128
#define BN 128
#define KC 32
#define NCHUNK (E_DIM / KC)        // 16
#define STRIDE 80                  // bytes per 32-bf16 row (64 + 16 pad)
#define ARR_SZ (128 * STRIDE)      // 10240
#define STAGE_SZ (4 * ARR_SZ)      // 40960
#define GEMM_SMEM (2 * STAGE_SZ)   // 81920

__global__ __launch_bounds__(256, 2) void mma_gemm_kernel(float* __restrict__ out) {
    extern __shared__ char smem[];
    const uint32_t sbase = smem_u32(smem);
    const int tid = threadIdx.x;
    const int lane = tid & 31;
    const int wid = tid >> 5;
    const int wm = wid & 3;        // m-quadrant: 32 rows each
    const int wn = wid >> 2;       // n-half: 64 cols each
    const int r0 = blockIdx.y * BM;
    const int c0 = blockIdx.x * BN;

    float acc[2][8][4];
    #pragma unroll
    for (int a = 0; a < 2; a++)
        #pragma unroll
        for (int b = 0; b < 8; b++)
            #pragma unroll
            for (int e = 0; e < 4; e++) acc[a][b][e] = 0.0f;

    // ---- chunk loader (cp.async): 4 arrays x 128 rows x 4 uint4 ----
    auto load_chunk = [&](int c, int stage) {
        uint32_t sb = sbase + (uint32_t)stage * STAGE_SZ;
        #pragma unroll
        for (int i = 0; i < 2; i++) {
            int slot = tid + i * 256;      // 0..511
            int row = slot >> 2;
            int u   = slot & 3;
            uint32_t so = (uint32_t)row * STRIDE + (uint32_t)u * 16;
            size_t ga = (size_t)(r0 + row) * E_DIM + c * KC + u * 8;
            size_t gb = (size_t)(c0 + row) * E_DIM + c * KC + u * 8;
            cp16(sb + so,              g_zhi + ga);
            cp16(sb + ARR_SZ + so,     g_zlo + ga);
            cp16(sb + 2 * ARR_SZ + so, g_bhi + gb);
            cp16(sb + 3 * ARR_SZ + so, g_blo + gb);
        }
        asm volatile("cp.async.commit_group;" ::: "memory");
    };

    // per-lane ldmatrix address components
    const uint32_t aRow  = (uint32_t)(wm * 32 + (lane & 15)) * STRIDE + ((lane >> 4) * 16);
    const uint32_t bRow  = (uint32_t)(wn * 64 + (lane & 7) + ((lane >> 4) << 3)) * STRIDE
                         + (((lane >> 3) & 1) * 16);

    auto compute = [&](int stage) {
        uint32_t sb = sbase + (uint32_t)stage * STAGE_SZ;
        uint32_t aHi = sb + aRow;
        uint32_t aLo = aHi + ARR_SZ;
        uint32_t bHi = sb + 2 * ARR_SZ + bRow;
        uint32_t bLo = bHi + ARR_SZ;
        #pragma unroll
        for (int ks = 0; ks < 2; ks++) {
            uint32_t ah[2][4], al[2][4];
            ldsm4(ah[0], aHi + ks * 32);
            ldsm4(ah[1], aHi + 16 * STRIDE + ks * 32);
            ldsm4(al[0], aLo + ks * 32);
            ldsm4(al[1], aLo + 16 * STRIDE + ks * 32);

            uint32_t bh[2][4], bl[2][4];
            ldsm4(bh[0], bHi + ks * 32);
            ldsm4(bl[0], bLo + ks * 32);

            #pragma unroll
            for (int np = 0; np < 4; np++) {
                const int cur = np & 1;
                const int nxt = cur ^ 1;
                if (np < 3) {   // prefetch next B tile while doing MMAs
                    ldsm4(bh[nxt], bHi + (np + 1) * 16 * STRIDE + ks * 32);
                    ldsm4(bl[nxt], bLo + (np + 1) * 16 * STRIDE + ks * 32);
                }
                // term-major: 4 independent accs per term (RAW distance 4)
                #pragma unroll
                for (int mt = 0; mt < 2; mt++)
                    #pragma unroll
                    for (int s = 0; s < 2; s++)
                        mma_bf16(acc[mt][np * 2 + s], ah[mt], bh[cur] + 2 * s);  // hi*hi
                #pragma unroll
                for (int mt = 0; mt < 2; mt++)
                    #pragma unroll
                    for (int s = 0; s < 2; s++)
                        mma_bf16(acc[mt][np * 2 + s], al[mt], bh[cur] + 2 * s);  // lo*hi
                #pragma unroll
                for (int mt = 0; mt < 2; mt++)
                    #pragma unroll
                    for (int s = 0; s < 2; s++)
                        mma_bf16(acc[mt][np * 2 + s], ah[mt], bl[cur] + 2 * s);  // hi*lo
            }
        }
    };

    // ---- pipelined mainloop: one barrier per chunk ----
    load_chunk(0, 0);
    #pragma unroll 1
    for (int c = 0; c < NCHUNK; c++) {
        asm volatile("cp.async.wait_group 0;" ::: "memory");   // chunk c landed
        __syncthreads();       // all warps done with compute(c-1) -> stage reusable
        if (c + 1 < NCHUNK) load_chunk(c + 1, (c + 1) & 1);    // overlaps compute(c)
        compute(c & 1);
    }

    // ---- epilogue: scale + scalar stores (OFF_D only 4B-aligned) ----
    float* D = out + OFF_D;
    const int gr = lane >> 2;
    const int gc = (lane & 3) * 2;
    #pragma unroll
    for (int mt = 0; mt < 2; mt++) {
        int rA = r0 + wm * 32 + mt * 16 + gr;
        int rB = rA + 8;
        float znA = g_znorm[rA];
        float znB = g_znorm[rB];
        #pragma unroll
        for (int n8 = 0; n8 < 8; n8++) {
            int cc = c0 + wn * 64 + n8 * 8 + gc;
            float cn0 = g_cbnorm[cc];
            float cn1 = g_cbnorm[cc + 1];
            float* a4 = acc[mt][n8];
            D[(size_t)rA * N_E + cc]     = a4[0] / (znA * cn0 + 1e-6f);
            D[(size_t)rA * N_E + cc + 1] = a4[1] / (znA * cn1 + 1e-6f);
            D[(size_t)rB * N_E + cc]     = a4[2] / (znB * cn0 + 1e-6f);
            D[(size_t)rB * N_E + cc + 1] = a4[3] / (znB * cn1 + 1e-6f);
        }
    }
}

// ---------------------------------------------------------------------------
// Polynomial exp on [-1,1] (degree-10 Taylor, FMA pipe; avoids MUFU wall)
// ---------------------------------------------------------------------------
__device__ __forceinline__ float exp_poly(float x) {
    const float c10 = 2.7557319e-7f, c9 = 2.7557319e-6f, c8 = 2.4801587e-5f;
    const float c7 = 1.9841270e-4f,  c6 = 1.3888889e-3f, c5 = 8.3333333e-3f;
    const float c4 = 4.1666668e-2f,  c3 = 1.6666667e-1f, c2 = 0.5f;
    float p = c10;
    p = fmaf(p, x, c9);
    p = fmaf(p, x, c8);
    p = fmaf(p, x, c7);
    p = fmaf(p, x, c6);
    p = fmaf(p, x, c5);
    p = fmaf(p, x, c4);
    p = fmaf(p, x, c3);
    p = fmaf(p, x, c2);
    p = fmaf(p, x, 1.0f);
    p = fmaf(p, x, 1.0f);
    return p;
}

// ---------------------------------------------------------------------------
// Fused per-row: argmax (first-index tie-break), histogram, idx output,
// softmax (poly exp, shift-free: d in [-1,1]), AND min_encodings one-hot row.
// ---------------------------------------------------------------------------
__global__ __launch_bounds__(256) void softmax_kernel(float* __restrict__ out) {
    __shared__ float sred[256];
    __shared__ int   sidx[256];

    int r = blockIdx.x;
    int t = threadIdx.x;
    const float* drow = out + OFF_D + (size_t)r * N_E;

    float e[32];
    float best = -2.0f;
    int bi = 0;
    float sum = 0.0f;
    #pragma unroll
    for (int j = 0; j < 32; j++) {
        int i = t + j * 256;
        float v = drow[i];
        if (v > best) { best = v; bi = i; }   // j ascending => first index kept
        float ev = exp_poly(v);
        e[j] = ev;
        sum += ev;
    }
    sred[t] = best; sidx[t] = bi;
    __syncthreads();
    for (int s = 128; s > 0; s >>= 1) {
        if (t < s) {
            float v = sred[t + s]; int ii = sidx[t + s];
            if (v > sred[t] || (v == sred[t] && ii < sidx[t])) {
                sred[t] = v; sidx[t] = ii;
            }
        }
        __syncthreads();
    }
    if (t == 0) {
        int idx = sidx[0];
        g_idx[r] = idx;
        atomicAdd(&g_counts[idx], 1);
        out[OFF_IDX + r] = (float)idx;
    }
    __syncthreads();

    sred[t] = sum;
    __syncthreads();
    for (int s = 128; s > 0; s >>= 1) {
        if (t < s) sred[t] += sred[t + s];
        __syncthreads();
    }
    float inv = 1.0f / sred[0];

    float* prow = out + OFF_PROB + (size_t)r * N_E;
    float* mrow = out + OFF_MINE + (size_t)r * N_E;
    #pragma unroll
    for (int j = 0; j < 32; j++) {
        int i = t + j * 256;
        prow[i] = e[j] * inv;
        mrow[i] = 0.0f;
    }
    __syncthreads();
    if (t == 0) mrow[sidx[0]] = 1.0f;
}

// ---------------------------------------------------------------------------
__global__ __launch_bounds__(128) void zq_kernel(const float* __restrict__ Z,
                                                 float* __restrict__ out) {
    int r = blockIdx.x;
    int t = threadIdx.x;
    int j = g_idx[r];
    const float* zr = Z    + (size_t)r * E_DIM;
    const float* cr = g_cb + (size_t)j * E_DIM;
    float* o = out + OFF_ZQ + (size_t)r * E_DIM;

    float dot = 0.0f, nc = 0.0f, nz = 0.0f;
    #pragma unroll
    for (int i = t; i < E_DIM; i += 128) {
        float zv = zr[i];
        float cv = cr[i];
        o[i] = zv + (cv - zv);
        dot += zv * cv;
        nc  += cv * cv;
        nz  += zv * zv;
    }
    __shared__ float sd_[128], sc_[128], sz_[128];
    sd_[t] = dot; sc_[t] = nc; sz_[t] = nz;
    __syncthreads();
    for (int s = 64; s > 0; s >>= 1) {
        if (t < s) { sd_[t] += sd_[t + s]; sc_[t] += sc_[t + s]; sz_[t] += sz_[t + s]; }
        __syncthreads();
    }
    if (t == 0) {
        g_cos[r] = sd_[0] / (fmaxf(sqrtf(sc_[0]), 1e-8f) * fmaxf(sqrtf(sz_[0]), 1e-8f));
    }
}

// ---------------------------------------------------------------------------
__global__ __launch_bounds__(256) void finalize_kernel(float* __restrict__ out) {
    int t = threadIdx.x;
    __shared__ float s1[256], s2[256], s3[256];

    float kl = 0.0f, ent = 0.0f, cs = 0.0f;
    const float invM  = 1.0f / (float)M_ROWS;
    const float invNE = 1.0f / (float)N_E;
    for (int j = t; j < N_E; j += 256) {
        float em = (float)g_counts[j] * invM;
        kl  += em * logf(invNE / (em + 1e-6f));
        ent += em * logf(em + 1e-6f);
    }
    for (int j = t; j < M_ROWS; j += 256) cs += g_cos[j];

    s1[t] = kl; s2[t] = ent; s3[t] = cs;
    __syncthreads();
    for (int s = 128; s > 0; s >>= 1) {
        if (t < s) { s1[t] += s1[t + s]; s2[t] += s2[t + s]; s3[t] += s3[t + s]; }
        __syncthreads();
    }
    if (t == 0) {
        float mc = s3[0] * invM;
        out[0] = (1.0f - mc) + 0.25f * (1.0f - mc);
        out[1] = 0.0f;
        out[2] = -s1[0];
        out[OFF_PERP] = expf(-s2[0]);
    }
}

// ---------------------------------------------------------------------------
extern "C" void kernel_launch(void* const* d_in, const int* in_sizes, int n_in,
                              void* d_out, int out_size) {
    const float* z = (const float*)d_in[0];
    const float* w = (const float*)d_in[1];
    float* out = (float*)d_out;

    cudaFuncSetAttribute(mma_gemm_kernel,
                         cudaFuncAttributeMaxDynamicSharedMemorySize, GEMM_SMEM);

    prep_cb_kernel<<<N_E, 256>>>(w);
    prep_z_kernel<<<M_ROWS, 256>>>(z);
    zero_counts_kernel<<<(N_E + 255) / 256, 256>>>();

    dim3 grid(N_E / BN, M_ROWS / BM);      // (64, 64)
    mma_gemm_kernel<<<grid, 256, GEMM_SMEM>>>(out);

    softmax_kernel<<<M_ROWS, 256>>>(out);

    zq_kernel<<<M_ROWS, 128>>>(z, out);
    finalize_kernel<<<1, 256>>>(out);
}

// round 8
// speedup vs baseline: 5.0320x; 1.1212x over previous
#include <cuda_runtime.h>
#include <cuda_bf16.h>
#include <math.h>
#include <stdint.h>

// Problem constants
#define M_ROWS 8192      // B*H*W
#define N_E    8192
#define E_DIM  512

// Output layout (flattened tuple, fp32)
#define OFF_PROB ((size_t)3)
#define OFF_D    (OFF_PROB + (size_t)M_ROWS * N_E)
#define OFF_ZQ   (OFF_D    + (size_t)M_ROWS * N_E)
#define OFF_PERP (OFF_ZQ   + (size_t)M_ROWS * E_DIM)
#define OFF_MINE (OFF_PERP + 1)
#define OFF_IDX  (OFF_MINE + (size_t)M_ROWS * N_E)

// ---------------------------------------------------------------------------
// Device scratch (no dynamic allocation allowed)
// ---------------------------------------------------------------------------
static __device__ float g_cb[(size_t)N_E * E_DIM];
static __device__ float g_cbnorm[N_E];
static __device__ float g_znorm[M_ROWS];
static __device__ int   g_idx[M_ROWS];
static __device__ int   g_counts[N_E];
static __device__ float g_cos[M_ROWS];
// bf16 hi/lo splits for tensor-core GEMM
static __device__ __align__(16) __nv_bfloat16 g_zhi[(size_t)M_ROWS * E_DIM];
static __device__ __align__(16) __nv_bfloat16 g_zlo[(size_t)M_ROWS * E_DIM];
static __device__ __align__(16) __nv_bfloat16 g_bhi[(size_t)N_E   * E_DIM];
static __device__ __align__(16) __nv_bfloat16 g_blo[(size_t)N_E   * E_DIM];

// ---------------------------------------------------------------------------
// PTX helpers (base ISA only: mma.sync / ldmatrix / cp.async)
// ---------------------------------------------------------------------------
__device__ __forceinline__ uint32_t smem_u32(const void* p) {
    uint32_t a;
    asm("{ .reg .u64 t; cvta.to.shared.u64 t, %1; cvt.u32.u64 %0, t; }"
        : "=r"(a) : "l"(p));
    return a;
}
__device__ __forceinline__ void cp16(uint32_t saddr, const void* g) {
    asm volatile("cp.async.cg.shared.global [%0], [%1], 16;"
                 :: "r"(saddr), "l"(g) : "memory");
}
__device__ __forceinline__ void ldsm4(uint32_t* r, uint32_t addr) {
    asm volatile("ldmatrix.sync.aligned.m8n8.x4.shared.b16 {%0,%1,%2,%3}, [%4];"
                 : "=r"(r[0]), "=r"(r[1]), "=r"(r[2]), "=r"(r[3]) : "r"(addr));
}
__device__ __forceinline__ void mma_bf16(float* c, const uint32_t* a, const uint32_t* b) {
    asm volatile(
        "mma.sync.aligned.m16n8k16.row.col.f32.bf16.bf16.f32 "
        "{%0,%1,%2,%3}, {%4,%5,%6,%7}, {%8,%9}, {%0,%1,%2,%3};"
        : "+f"(c[0]), "+f"(c[1]), "+f"(c[2]), "+f"(c[3])
        : "r"(a[0]), "r"(a[1]), "r"(a[2]), "r"(a[3]), "r"(b[0]), "r"(b[1]));
}

// ---------------------------------------------------------------------------
// Codebook prep: cb = w/||w||, cb_norm = ||cb||, bf16 hi/lo split
// ---------------------------------------------------------------------------
__global__ __launch_bounds__(256) void prep_cb_kernel(const float* __restrict__ w) {
    int r = blockIdx.x;
    int t = threadIdx.x;
    const float* row = w + (size_t)r * E_DIM;
    float v0 = row[t];
    float v1 = row[t + 256];

    __shared__ float sm[256];
    sm[t] = v0 * v0 + v1 * v1;
    __syncthreads();
    #pragma unroll
    for (int s = 128; s > 0; s >>= 1) {
        if (t < s) sm[t] += sm[t + s];
        __syncthreads();
    }
    float norm = sqrtf(sm[0]);
    __syncthreads();

    float c0 = v0 / norm;
    float c1 = v1 / norm;
    size_t base = (size_t)r * E_DIM;
    g_cb[base + t]       = c0;
    g_cb[base + t + 256] = c1;

    __nv_bfloat16 h0 = __float2bfloat16(c0);
    __nv_bfloat16 h1 = __float2bfloat16(c1);
    g_bhi[base + t]       = h0;
    g_bhi[base + t + 256] = h1;
    g_blo[base + t]       = __float2bfloat16(c0 - __bfloat162float(h0));
    g_blo[base + t + 256] = __float2bfloat16(c1 - __bfloat162float(h1));

    sm[t] = c0 * c0 + c1 * c1;
    __syncthreads();
    #pragma unroll
    for (int s = 128; s > 0; s >>= 1) {
        if (t < s) sm[t] += sm[t + s];
        __syncthreads();
    }
    if (t == 0) g_cbnorm[r] = sqrtf(sm[0]);
}

// ---------------------------------------------------------------------------
// z prep: row norms + bf16 hi/lo split
// ---------------------------------------------------------------------------
__global__ __launch_bounds__(256) void prep_z_kernel(const float* __restrict__ z) {
    int r = blockIdx.x;
    int t = threadIdx.x;
    const float* row = z + (size_t)r * E_DIM;
    float v0 = row[t];
    float v1 = row[t + 256];

    size_t base = (size_t)r * E_DIM;
    __nv_bfloat16 h0 = __float2bfloat16(v0);
    __nv_bfloat16 h1 = __float2bfloat16(v1);
    g_zhi[base + t]       = h0;
    g_zhi[base + t + 256] = h1;
    g_zlo[base + t]       = __float2bfloat16(v0 - __bfloat162float(h0));
    g_zlo[base + t + 256] = __float2bfloat16(v1 - __bfloat162float(h1));

    __shared__ float sm[256];
    sm[t] = v0 * v0 + v1 * v1;
    __syncthreads();
    #pragma unroll
    for (int s = 128; s > 0; s >>= 1) {
        if (t < s) sm[t] += sm[t + s];
        __syncthreads();
    }
    if (t == 0) g_znorm[r] = sqrtf(sm[0]);
}

__global__ void zero_counts_kernel() {
    int i = blockIdx.x * 256 + threadIdx.x;
    if (i < N_E) g_counts[i] = 0;
}

// ---------------------------------------------------------------------------
// mma.sync GEMM (3-term bf16 split): tile 128x128, K chunks of 32,
// 3-stage cp.async pipeline, loads issued 2 chunks ahead.
// CORRECT ordering: wait_group (own copies) -> __syncthreads (global
// visibility + stage retire) -> issue next load -> compute.
// XOR swizzle (c ^= row>>1) on 64B rows: conflict-free, no padding.
// 96KB smem/CTA -> 2 CTAs/SM.
// ---------------------------------------------------------------------------
#define BM 128
#define BN 128
#define KC 32
#define NCHUNK (E_DIM / KC)        // 16
#define ROWB 64                    // bytes per 32-bf16 row (no pad)
#define ARR_SZ (128 * ROWB)        // 8192
#define STAGE_SZ (4 * ARR_SZ)      // 32768
#define NSTAGE 3
#define GEMM_SMEM (NSTAGE * STAGE_SZ)  // 98304

// swizzled byte offset within one array for (row, c16) ; c16 in 0..3
__device__ __forceinline__ uint32_t swz(uint32_t row, uint32_t c16) {
    return row * ROWB + (((c16 ^ (row >> 1)) & 3u) << 4);
}

__global__ __launch_bounds__(256, 2) void mma_gemm_kernel(float* __restrict__ out) {
    extern __shared__ char smem[];
    const uint32_t sbase = smem_u32(smem);
    const int tid = threadIdx.x;
    const int lane = tid & 31;
    const int wid = tid >> 5;
    const int wm = wid & 3;        // m-quadrant: 32 rows each
    const int wn = wid >> 2;       // n-half: 64 cols each
    const int r0 = blockIdx.y * BM;
    const int c0 = blockIdx.x * BN;

    float acc[2][8][4];
    #pragma unroll
    for (int a = 0; a < 2; a++)
        #pragma unroll
        for (int b = 0; b < 8; b++)
            #pragma unroll
            for (int e = 0; e < 4; e++) acc[a][b][e] = 0.0f;

    // ---- chunk loader (cp.async): 4 arrays x 128 rows x 4 x 16B ----
    auto load_chunk = [&](int c, int stage) {
        uint32_t sb = sbase + (uint32_t)stage * STAGE_SZ;
        #pragma unroll
        for (int i = 0; i < 2; i++) {
            int slot = tid + i * 256;      // 0..511
            uint32_t row = (uint32_t)slot >> 2;
            uint32_t u   = (uint32_t)slot & 3;
            uint32_t so = swz(row, u);
            size_t ga = (size_t)(r0 + row) * E_DIM + c * KC + u * 8;
            size_t gb = (size_t)(c0 + row) * E_DIM + c * KC + u * 8;
            cp16(sb + so,              g_zhi + ga);
            cp16(sb + ARR_SZ + so,     g_zlo + ga);
            cp16(sb + 2 * ARR_SZ + so, g_bhi + gb);
            cp16(sb + 3 * ARR_SZ + so, g_blo + gb);
        }
        asm volatile("cp.async.commit_group;" ::: "memory");
    };

    // per-lane fragment addressing (swizzle XOR is invariant under +16 rows)
    const uint32_t rowA = (uint32_t)(wm * 32 + (lane & 15));
    const uint32_t rowB = (uint32_t)(wn * 64 + (lane & 7) + ((lane >> 4) << 3));
    const uint32_t xA = (rowA >> 1) & 3u;
    const uint32_t xB = (rowB >> 1) & 3u;
    const uint32_t cA0 = (uint32_t)(lane >> 4);        // 0..1
    const uint32_t cB0 = (uint32_t)((lane >> 3) & 1);  // 0..1
    const uint32_t aBase = rowA * ROWB;
    const uint32_t bBase = rowB * ROWB;

    auto compute = [&](int stage) {
        uint32_t sb = sbase + (uint32_t)stage * STAGE_SZ;
        uint32_t Ahi = sb;
        uint32_t Alo = sb + ARR_SZ;
        uint32_t Bhi = sb + 2 * ARR_SZ;
        uint32_t Blo = sb + 3 * ARR_SZ;
        #pragma unroll
        for (int ks = 0; ks < 2; ks++) {
            uint32_t aOff = aBase + (((cA0 + 2 * ks) ^ xA) & 3u) * 16;
            uint32_t bOff = bBase + (((cB0 + 2 * ks) ^ xB) & 3u) * 16;

            uint32_t ah[2][4], al[2][4];
            ldsm4(ah[0], Ahi + aOff);
            ldsm4(ah[1], Ahi + aOff + 16 * ROWB);
            ldsm4(al[0], Alo + aOff);
            ldsm4(al[1], Alo + aOff + 16 * ROWB);

            uint32_t bh[2][4], bl[2][4];
            ldsm4(bh[0], Bhi + bOff);
            ldsm4(bl[0], Blo + bOff);

            #pragma unroll
            for (int np = 0; np < 4; np++) {
                const int cur = np & 1;
                const int nxt = cur ^ 1;
                if (np < 3) {   // prefetch next B tile while doing MMAs
                    ldsm4(bh[nxt], Bhi + bOff + (np + 1) * 16 * ROWB);
                    ldsm4(bl[nxt], Blo + bOff + (np + 1) * 16 * ROWB);
                }
                #pragma unroll
                for (int mt = 0; mt < 2; mt++)
                    #pragma unroll
                    for (int s = 0; s < 2; s++)
                        mma_bf16(acc[mt][np * 2 + s], ah[mt], bh[cur] + 2 * s);  // hi*hi
                #pragma unroll
                for (int mt = 0; mt < 2; mt++)
                    #pragma unroll
                    for (int s = 0; s < 2; s++)
                        mma_bf16(acc[mt][np * 2 + s], al[mt], bh[cur] + 2 * s);  // lo*hi
                #pragma unroll
                for (int mt = 0; mt < 2; mt++)
                    #pragma unroll
                    for (int s = 0; s < 2; s++)
                        mma_bf16(acc[mt][np * 2 + s], ah[mt], bl[cur] + 2 * s);  // hi*lo
            }
        }
    };

    // ---- 3-stage pipelined mainloop, loads 2 chunks ahead ----
    load_chunk(0, 0);
    load_chunk(1, 1);
    #pragma unroll 1
    for (int c = 0; c < NCHUNK; c++) {
        // own chunk-c copies done (issued 2 iterations ago -> near-free wait;
        // does NOT wait on chunk c+1)
        if (c + 1 < NCHUNK) {
            asm volatile("cp.async.wait_group 1;" ::: "memory");
        } else {
            asm volatile("cp.async.wait_group 0;" ::: "memory");
        }
        // all threads waited -> chunk c globally visible; all warps past
        // compute(c-1) -> stage (c+2)%3 reusable
        __syncthreads();
        if (c + 2 < NCHUNK) load_chunk(c + 2, (c + 2) % NSTAGE);
        compute(c % NSTAGE);
    }

    // ---- epilogue: scale + scalar stores (OFF_D only 4B-aligned) ----
    float* D = out + OFF_D;
    const int gr = lane >> 2;
    const int gc = (lane & 3) * 2;
    #pragma unroll
    for (int mt = 0; mt < 2; mt++) {
        int rA = r0 + wm * 32 + mt * 16 + gr;
        int rB = rA + 8;
        float znA = g_znorm[rA];
        float znB = g_znorm[rB];
        #pragma unroll
        for (int n8 = 0; n8 < 8; n8++) {
            int cc = c0 + wn * 64 + n8 * 8 + gc;
            float cn0 = g_cbnorm[cc];
            float cn1 = g_cbnorm[cc + 1];
            float* a4 = acc[mt][n8];
            D[(size_t)rA * N_E + cc]     = a4[0] / (znA * cn0 + 1e-6f);
            D[(size_t)rA * N_E + cc + 1] = a4[1] / (znA * cn1 + 1e-6f);
            D[(size_t)rB * N_E + cc]     = a4[2] / (znB * cn0 + 1e-6f);
            D[(size_t)rB * N_E + cc + 1] = a4[3] / (znB * cn1 + 1e-6f);
        }
    }
}

// ---------------------------------------------------------------------------
// Polynomial exp on [-1,1] (degree-10 Taylor, FMA pipe; avoids MUFU wall)
// ---------------------------------------------------------------------------
__device__ __forceinline__ float exp_poly(float x) {
    const float c10 = 2.7557319e-7f, c9 = 2.7557319e-6f, c8 = 2.4801587e-5f;
    const float c7 = 1.9841270e-4f,  c6 = 1.3888889e-3f, c5 = 8.3333333e-3f;
    const float c4 = 4.1666668e-2f,  c3 = 1.6666667e-1f, c2 = 0.5f;
    float p = c10;
    p = fmaf(p, x, c9);
    p = fmaf(p, x, c8);
    p = fmaf(p, x, c7);
    p = fmaf(p, x, c6);
    p = fmaf(p, x, c5);
    p = fmaf(p, x, c4);
    p = fmaf(p, x, c3);
    p = fmaf(p, x, c2);
    p = fmaf(p, x, 1.0f);
    p = fmaf(p, x, 1.0f);
    return p;
}

// ---------------------------------------------------------------------------
// Fused per-row: argmax (first-index tie-break), histogram, idx output,
// softmax (poly exp, shift-free: d in [-1,1]), AND min_encodings one-hot row.
// ---------------------------------------------------------------------------
__global__ __launch_bounds__(256) void softmax_kernel(float* __restrict__ out) {
    __shared__ float sred[256];
    __shared__ int   sidx[256];

    int r = blockIdx.x;
    int t = threadIdx.x;
    const float* drow = out + OFF_D + (size_t)r * N_E;

    float e[32];
    float best = -2.0f;
    int bi = 0;
    float sum = 0.0f;
    #pragma unroll
    for (int j = 0; j < 32; j++) {
        int i = t + j * 256;
        float v = drow[i];
        if (v > best) { best = v; bi = i; }   // j ascending => first index kept
        float ev = exp_poly(v);
        e[j] = ev;
        sum += ev;
    }
    sred[t] = best; sidx[t] = bi;
    __syncthreads();
    for (int s = 128; s > 0; s >>= 1) {
        if (t < s) {
            float v = sred[t + s]; int ii = sidx[t + s];
            if (v > sred[t] || (v == sred[t] && ii < sidx[t])) {
                sred[t] = v; sidx[t] = ii;
            }
        }
        __syncthreads();
    }
    if (t == 0) {
        int idx = sidx[0];
        g_idx[r] = idx;
        atomicAdd(&g_counts[idx], 1);
        out[OFF_IDX + r] = (float)idx;
    }
    __syncthreads();

    sred[t] = sum;
    __syncthreads();
    for (int s = 128; s > 0; s >>= 1) {
        if (t < s) sred[t] += sred[t + s];
        __syncthreads();
    }
    float inv = 1.0f / sred[0];

    float* prow = out + OFF_PROB + (size_t)r * N_E;
    float* mrow = out + OFF_MINE + (size_t)r * N_E;
    #pragma unroll
    for (int j = 0; j < 32; j++) {
        int i = t + j * 256;
        prow[i] = e[j] * inv;
        mrow[i] = 0.0f;
    }
    __syncthreads();
    if (t == 0) mrow[sidx[0]] = 1.0f;
}

// ---------------------------------------------------------------------------
__global__ __launch_bounds__(128) void zq_kernel(const float* __restrict__ Z,
                                                 float* __restrict__ out) {
    int r = blockIdx.x;
    int t = threadIdx.x;
    int j = g_idx[r];
    const float* zr = Z    + (size_t)r * E_DIM;
    const float* cr = g_cb + (size_t)j * E_DIM;
    float* o = out + OFF_ZQ + (size_t)r * E_DIM;

    float dot = 0.0f, nc = 0.0f, nz = 0.0f;
    #pragma unroll
    for (int i = t; i < E_DIM; i += 128) {
        float zv = zr[i];
        float cv = cr[i];
        o[i] = zv + (cv - zv);
        dot += zv * cv;
        nc  += cv * cv;
        nz  += zv * zv;
    }
    __shared__ float sd_[128], sc_[128], sz_[128];
    sd_[t] = dot; sc_[t] = nc; sz_[t] = nz;
    __syncthreads();
    for (int s = 64; s > 0; s >>= 1) {
        if (t < s) { sd_[t] += sd_[t + s]; sc_[t] += sc_[t + s]; sz_[t] += sz_[t + s]; }
        __syncthreads();
    }
    if (t == 0) {
        g_cos[r] = sd_[0] / (fmaxf(sqrtf(sc_[0]), 1e-8f) * fmaxf(sqrtf(sz_[0]), 1e-8f));
    }
}

// ---------------------------------------------------------------------------
__global__ __launch_bounds__(256) void finalize_kernel(float* __restrict__ out) {
    int t = threadIdx.x;
    __shared__ float s1[256], s2[256], s3[256];

    float kl = 0.0f, ent = 0.0f, cs = 0.0f;
    const float invM  = 1.0f / (float)M_ROWS;
    const float invNE = 1.0f / (float)N_E;
    for (int j = t; j < N_E; j += 256) {
        float em = (float)g_counts[j] * invM;
        kl  += em * logf(invNE / (em + 1e-6f));
        ent += em * logf(em + 1e-6f);
    }
    for (int j = t; j < M_ROWS; j += 256) cs += g_cos[j];

    s1[t] = kl; s2[t] = ent; s3[t] = cs;
    __syncthreads();
    for (int s = 128; s > 0; s >>= 1) {
        if (t < s) { s1[t] += s1[t + s]; s2[t] += s2[t + s]; s3[t] += s3[t + s]; }
        __syncthreads();
    }
    if (t == 0) {
        float mc = s3[0] * invM;
        out[0] = (1.0f - mc) + 0.25f * (1.0f - mc);
        out[1] = 0.0f;
        out[2] = -s1[0];
        out[OFF_PERP] = expf(-s2[0]);
    }
}

// ---------------------------------------------------------------------------
extern "C" void kernel_launch(void* const* d_in, const int* in_sizes, int n_in,
                              void* d_out, int out_size) {
    const float* z = (const float*)d_in[0];
    const float* w = (const float*)d_in[1];
    float* out = (float*)d_out;

    cudaFuncSetAttribute(mma_gemm_kernel,
                         cudaFuncAttributeMaxDynamicSharedMemorySize, GEMM_SMEM);

    prep_cb_kernel<<<N_E, 256>>>(w);
    prep_z_kernel<<<M_ROWS, 256>>>(z);
    zero_counts_kernel<<<(N_E + 255) / 256, 256>>>();

    dim3 grid(N_E / BN, M_ROWS / BM);      // (64, 64)
    mma_gemm_kernel<<<grid, 256, GEMM_SMEM>>>(out);

    softmax_kernel<<<M_ROWS, 256>>>(out);

    zq_kernel<<<M_ROWS, 128>>>(z, out);
    finalize_kernel<<<1, 256>>>(out);
}

// round 9
// speedup vs baseline: 5.0854x; 1.0106x over previous
#include <cuda_runtime.h>
#include <cuda_bf16.h>
#include <math.h>
#include <stdint.h>

// Problem constants
#define M_ROWS 8192      // B*H*W
#define N_E    8192
#define E_DIM  512

// Output layout (flattened tuple, fp32)
#define OFF_PROB ((size_t)3)
#define OFF_D    (OFF_PROB + (size_t)M_ROWS * N_E)
#define OFF_ZQ   (OFF_D    + (size_t)M_ROWS * N_E)
#define OFF_PERP (OFF_ZQ   + (size_t)M_ROWS * E_DIM)
#define OFF_MINE (OFF_PERP + 1)
#define OFF_IDX  (OFF_MINE + (size_t)M_ROWS * N_E)

// ---------------------------------------------------------------------------
// Device scratch (no dynamic allocation allowed)
// ---------------------------------------------------------------------------
static __device__ float g_cb[(size_t)N_E * E_DIM];
static __device__ float g_cbnorm[N_E];
static __device__ float g_znorm[M_ROWS];
static __device__ int   g_idx[M_ROWS];
static __device__ int   g_counts[N_E];
static __device__ float g_cos[M_ROWS];
// bf16 hi/lo splits for tensor-core GEMM
static __device__ __align__(16) __nv_bfloat16 g_zhi[(size_t)M_ROWS * E_DIM];
static __device__ __align__(16) __nv_bfloat16 g_zlo[(size_t)M_ROWS * E_DIM];
static __device__ __align__(16) __nv_bfloat16 g_bhi[(size_t)N_E   * E_DIM];
static __device__ __align__(16) __nv_bfloat16 g_blo[(size_t)N_E   * E_DIM];

// ---------------------------------------------------------------------------
// PTX helpers (base ISA only: mma.sync / ldmatrix / cp.async)
// ---------------------------------------------------------------------------
__device__ __forceinline__ uint32_t smem_u32(const void* p) {
    uint32_t a;
    asm("{ .reg .u64 t; cvta.to.shared.u64 t, %1; cvt.u32.u64 %0, t; }"
        : "=r"(a) : "l"(p));
    return a;
}
__device__ __forceinline__ void cp16(uint32_t saddr, const void* g) {
    asm volatile("cp.async.cg.shared.global [%0], [%1], 16;"
                 :: "r"(saddr), "l"(g) : "memory");
}
__device__ __forceinline__ void ldsm4(uint32_t* r, uint32_t addr) {
    asm volatile("ldmatrix.sync.aligned.m8n8.x4.shared.b16 {%0,%1,%2,%3}, [%4];"
                 : "=r"(r[0]), "=r"(r[1]), "=r"(r[2]), "=r"(r[3]) : "r"(addr));
}
__device__ __forceinline__ void mma_bf16(float* c, const uint32_t* a, const uint32_t* b) {
    asm volatile(
        "mma.sync.aligned.m16n8k16.row.col.f32.bf16.bf16.f32 "
        "{%0,%1,%2,%3}, {%4,%5,%6,%7}, {%8,%9}, {%0,%1,%2,%3};"
        : "+f"(c[0]), "+f"(c[1]), "+f"(c[2]), "+f"(c[3])
        : "r"(a[0]), "r"(a[1]), "r"(a[2]), "r"(a[3]), "r"(b[0]), "r"(b[1]));
}

// ---------------------------------------------------------------------------
// Codebook prep: cb = w/||w||, cb_norm = ||cb||, bf16 hi/lo split
// ---------------------------------------------------------------------------
__global__ __launch_bounds__(256) void prep_cb_kernel(const float* __restrict__ w) {
    int r = blockIdx.x;
    int t = threadIdx.x;
    const float* row = w + (size_t)r * E_DIM;
    float v0 = row[t];
    float v1 = row[t + 256];

    __shared__ float sm[256];
    sm[t] = v0 * v0 + v1 * v1;
    __syncthreads();
    #pragma unroll
    for (int s = 128; s > 0; s >>= 1) {
        if (t < s) sm[t] += sm[t + s];
        __syncthreads();
    }
    float norm = sqrtf(sm[0]);
    __syncthreads();

    float c0 = v0 / norm;
    float c1 = v1 / norm;
    size_t base = (size_t)r * E_DIM;
    g_cb[base + t]       = c0;
    g_cb[base + t + 256] = c1;

    __nv_bfloat16 h0 = __float2bfloat16(c0);
    __nv_bfloat16 h1 = __float2bfloat16(c1);
    g_bhi[base + t]       = h0;
    g_bhi[base + t + 256] = h1;
    g_blo[base + t]       = __float2bfloat16(c0 - __bfloat162float(h0));
    g_blo[base + t + 256] = __float2bfloat16(c1 - __bfloat162float(h1));

    sm[t] = c0 * c0 + c1 * c1;
    __syncthreads();
    #pragma unroll
    for (int s = 128; s > 0; s >>= 1) {
        if (t < s) sm[t] += sm[t + s];
        __syncthreads();
    }
    if (t == 0) g_cbnorm[r] = sqrtf(sm[0]);
}

// ---------------------------------------------------------------------------
// z prep: row norms + bf16 hi/lo split (+ counts zeroing folded in)
// ---------------------------------------------------------------------------
__global__ __launch_bounds__(256) void prep_z_kernel(const float* __restrict__ z) {
    int r = blockIdx.x;
    int t = threadIdx.x;
    const float* row = z + (size_t)r * E_DIM;
    float v0 = row[t];
    float v1 = row[t + 256];

    size_t base = (size_t)r * E_DIM;
    __nv_bfloat16 h0 = __float2bfloat16(v0);
    __nv_bfloat16 h1 = __float2bfloat16(v1);
    g_zhi[base + t]       = h0;
    g_zhi[base + t + 256] = h1;
    g_zlo[base + t]       = __float2bfloat16(v0 - __bfloat162float(h0));
    g_zlo[base + t + 256] = __float2bfloat16(v1 - __bfloat162float(h1));

    if (r < N_E / 256) g_counts[r * 256 + t] = 0;   // 8192 rows cover 8192 counts

    __shared__ float sm[256];
    sm[t] = v0 * v0 + v1 * v1;
    __syncthreads();
    #pragma unroll
    for (int s = 128; s > 0; s >>= 1) {
        if (t < s) sm[t] += sm[t + s];
        __syncthreads();
    }
    if (t == 0) g_znorm[r] = sqrtf(sm[0]);
}

// ---------------------------------------------------------------------------
// mma.sync GEMM (3-term bf16 split): tile 128x128, K chunks of 32,
// 3-stage cp.async pipeline, loads issued 2 chunks ahead.
// Ordering: wait_group (own copies) -> __syncthreads -> issue load -> compute.
// XOR swizzle (c ^= row>>1) on 64B rows. 96KB smem/CTA -> 2 CTAs/SM.
// Epilogue also zeroes this CTA's min_encodings tile (uses idle DRAM BW).
// ---------------------------------------------------------------------------
#define BM 128
#define BN 128
#define KC 32
#define NCHUNK (E_DIM / KC)        // 16
#define ROWB 64                    // bytes per 32-bf16 row (no pad)
#define ARR_SZ (128 * ROWB)        // 8192
#define STAGE_SZ (4 * ARR_SZ)      // 32768
#define NSTAGE 3
#define GEMM_SMEM (NSTAGE * STAGE_SZ)  // 98304

// swizzled byte offset within one array for (row, c16) ; c16 in 0..3
__device__ __forceinline__ uint32_t swz(uint32_t row, uint32_t c16) {
    return row * ROWB + (((c16 ^ (row >> 1)) & 3u) << 4);
}

__global__ __launch_bounds__(256, 2) void mma_gemm_kernel(float* __restrict__ out) {
    extern __shared__ char smem[];
    const uint32_t sbase = smem_u32(smem);
    const int tid = threadIdx.x;
    const int lane = tid & 31;
    const int wid = tid >> 5;
    const int wm = wid & 3;        // m-quadrant: 32 rows each
    const int wn = wid >> 2;       // n-half: 64 cols each
    const int r0 = blockIdx.y * BM;
    const int c0 = blockIdx.x * BN;

    float acc[2][8][4];
    #pragma unroll
    for (int a = 0; a < 2; a++)
        #pragma unroll
        for (int b = 0; b < 8; b++)
            #pragma unroll
            for (int e = 0; e < 4; e++) acc[a][b][e] = 0.0f;

    // ---- chunk loader (cp.async): 4 arrays x 128 rows x 4 x 16B ----
    auto load_chunk = [&](int c, int stage) {
        uint32_t sb = sbase + (uint32_t)stage * STAGE_SZ;
        #pragma unroll
        for (int i = 0; i < 2; i++) {
            int slot = tid + i * 256;      // 0..511
            uint32_t row = (uint32_t)slot >> 2;
            uint32_t u   = (uint32_t)slot & 3;
            uint32_t so = swz(row, u);
            size_t ga = (size_t)(r0 + row) * E_DIM + c * KC + u * 8;
            size_t gb = (size_t)(c0 + row) * E_DIM + c * KC + u * 8;
            cp16(sb + so,              g_zhi + ga);
            cp16(sb + ARR_SZ + so,     g_zlo + ga);
            cp16(sb + 2 * ARR_SZ + so, g_bhi + gb);
            cp16(sb + 3 * ARR_SZ + so, g_blo + gb);
        }
        asm volatile("cp.async.commit_group;" ::: "memory");
    };

    // per-lane fragment addressing (swizzle XOR is invariant under +16 rows)
    const uint32_t rowA = (uint32_t)(wm * 32 + (lane & 15));
    const uint32_t rowB = (uint32_t)(wn * 64 + (lane & 7) + ((lane >> 4) << 3));
    const uint32_t xA = (rowA >> 1) & 3u;
    const uint32_t xB = (rowB >> 1) & 3u;
    const uint32_t cA0 = (uint32_t)(lane >> 4);        // 0..1
    const uint32_t cB0 = (uint32_t)((lane >> 3) & 1);  // 0..1
    const uint32_t aBase = rowA * ROWB;
    const uint32_t bBase = rowB * ROWB;

    auto compute = [&](int stage) {
        uint32_t sb = sbase + (uint32_t)stage * STAGE_SZ;
        uint32_t Ahi = sb;
        uint32_t Alo = sb + ARR_SZ;
        uint32_t Bhi = sb + 2 * ARR_SZ;
        uint32_t Blo = sb + 3 * ARR_SZ;
        #pragma unroll
        for (int ks = 0; ks < 2; ks++) {
            uint32_t aOff = aBase + (((cA0 + 2 * ks) ^ xA) & 3u) * 16;
            uint32_t bOff = bBase + (((cB0 + 2 * ks) ^ xB) & 3u) * 16;

            uint32_t ah[2][4], al[2][4];
            ldsm4(ah[0], Ahi + aOff);
            ldsm4(ah[1], Ahi + aOff + 16 * ROWB);
            ldsm4(al[0], Alo + aOff);
            ldsm4(al[1], Alo + aOff + 16 * ROWB);

            uint32_t bh[2][4], bl[2][4];
            ldsm4(bh[0], Bhi + bOff);
            ldsm4(bl[0], Blo + bOff);

            #pragma unroll
            for (int np = 0; np < 4; np++) {
                const int cur = np & 1;
                const int nxt = cur ^ 1;
                if (np < 3) {   // prefetch next B tile while doing MMAs
                    ldsm4(bh[nxt], Bhi + bOff + (np + 1) * 16 * ROWB);
                    ldsm4(bl[nxt], Blo + bOff + (np + 1) * 16 * ROWB);
                }
                #pragma unroll
                for (int mt = 0; mt < 2; mt++)
                    #pragma unroll
                    for (int s = 0; s < 2; s++)
                        mma_bf16(acc[mt][np * 2 + s], ah[mt], bh[cur] + 2 * s);  // hi*hi
                #pragma unroll
                for (int mt = 0; mt < 2; mt++)
                    #pragma unroll
                    for (int s = 0; s < 2; s++)
                        mma_bf16(acc[mt][np * 2 + s], al[mt], bh[cur] + 2 * s);  // lo*hi
                #pragma unroll
                for (int mt = 0; mt < 2; mt++)
                    #pragma unroll
                    for (int s = 0; s < 2; s++)
                        mma_bf16(acc[mt][np * 2 + s], ah[mt], bl[cur] + 2 * s);  // hi*lo
            }
        }
    };

    // ---- 3-stage pipelined mainloop, loads 2 chunks ahead ----
    load_chunk(0, 0);
    load_chunk(1, 1);
    #pragma unroll 1
    for (int c = 0; c < NCHUNK; c++) {
        if (c + 1 < NCHUNK) {
            asm volatile("cp.async.wait_group 1;" ::: "memory");  // chunk c done
        } else {
            asm volatile("cp.async.wait_group 0;" ::: "memory");
        }
        __syncthreads();   // chunk c visible to all; stage (c+2)%3 reusable
        if (c + 2 < NCHUNK) load_chunk(c + 2, (c + 2) % NSTAGE);
        compute(c % NSTAGE);
    }

    // ---- epilogue: scale + scalar stores (OFF_D only 4B-aligned) ----
    float* D = out + OFF_D;
    const int gr = lane >> 2;
    const int gc = (lane & 3) * 2;
    #pragma unroll
    for (int mt = 0; mt < 2; mt++) {
        int rA = r0 + wm * 32 + mt * 16 + gr;
        int rB = rA + 8;
        float znA = g_znorm[rA];
        float znB = g_znorm[rB];
        #pragma unroll
        for (int n8 = 0; n8 < 8; n8++) {
            int cc = c0 + wn * 64 + n8 * 8 + gc;
            float cn0 = g_cbnorm[cc];
            float cn1 = g_cbnorm[cc + 1];
            float* a4 = acc[mt][n8];
            D[(size_t)rA * N_E + cc]     = a4[0] / (znA * cn0 + 1e-6f);
            D[(size_t)rA * N_E + cc + 1] = a4[1] / (znA * cn1 + 1e-6f);
            D[(size_t)rB * N_E + cc]     = a4[2] / (znB * cn0 + 1e-6f);
            D[(size_t)rB * N_E + cc + 1] = a4[3] / (znB * cn1 + 1e-6f);
        }
    }

    // ---- zero this CTA's min_encodings tile (idle DRAM bandwidth) ----
    // softmax later writes the single 1.0 per row.
    float* MINE = out + OFF_MINE;
    #pragma unroll
    for (int k = 0; k < (BM * BN) / 256; k++) {
        int e = tid + k * 256;
        int row = e >> 7;            // BN = 128
        int col = e & 127;
        MINE[(size_t)(r0 + row) * N_E + c0 + col] = 0.0f;
    }
}

// ---------------------------------------------------------------------------
// Polynomial exp on [-1,1] (degree-10 Taylor, FMA pipe; avoids MUFU wall)
// ---------------------------------------------------------------------------
__device__ __forceinline__ float exp_poly(float x) {
    const float c10 = 2.7557319e-7f, c9 = 2.7557319e-6f, c8 = 2.4801587e-5f;
    const float c7 = 1.9841270e-4f,  c6 = 1.3888889e-3f, c5 = 8.3333333e-3f;
    const float c4 = 4.1666668e-2f,  c3 = 1.6666667e-1f, c2 = 0.5f;
    float p = c10;
    p = fmaf(p, x, c9);
    p = fmaf(p, x, c8);
    p = fmaf(p, x, c7);
    p = fmaf(p, x, c6);
    p = fmaf(p, x, c5);
    p = fmaf(p, x, c4);
    p = fmaf(p, x, c3);
    p = fmaf(p, x, c2);
    p = fmaf(p, x, 1.0f);
    p = fmaf(p, x, 1.0f);
    return p;
}

// ---------------------------------------------------------------------------
// Fused per-row: argmax (first-index tie-break), histogram, idx output,
// softmax (poly exp, shift-free: d in [-1,1]), single one-hot 1.0 scatter
// (zeros already laid down by the GEMM epilogue).
// ---------------------------------------------------------------------------
__global__ __launch_bounds__(256) void softmax_kernel(float* __restrict__ out) {
    __shared__ float sred[256];
    __shared__ int   sidx[256];

    int r = blockIdx.x;
    int t = threadIdx.x;
    const float* drow = out + OFF_D + (size_t)r * N_E;

    float e[32];
    float best = -2.0f;
    int bi = 0;
    float sum = 0.0f;
    #pragma unroll
    for (int j = 0; j < 32; j++) {
        int i = t + j * 256;
        float v = drow[i];
        if (v > best) { best = v; bi = i; }   // j ascending => first index kept
        float ev = exp_poly(v);
        e[j] = ev;
        sum += ev;
    }
    sred[t] = best; sidx[t] = bi;
    __syncthreads();
    for (int s = 128; s > 0; s >>= 1) {
        if (t < s) {
            float v = sred[t + s]; int ii = sidx[t + s];
            if (v > sred[t] || (v == sred[t] && ii < sidx[t])) {
                sred[t] = v; sidx[t] = ii;
            }
        }
        __syncthreads();
    }
    if (t == 0) {
        int idx = sidx[0];
        g_idx[r] = idx;
        atomicAdd(&g_counts[idx], 1);
        out[OFF_IDX + r] = (float)idx;
        out[OFF_MINE + (size_t)r * N_E + idx] = 1.0f;
    }
    __syncthreads();

    sred[t] = sum;
    __syncthreads();
    for (int s = 128; s > 0; s >>= 1) {
        if (t < s) sred[t] += sred[t + s];
        __syncthreads();
    }
    float inv = 1.0f / sred[0];

    float* prow = out + OFF_PROB + (size_t)r * N_E;
    #pragma unroll
    for (int j = 0; j < 32; j++) prow[t + j * 256] = e[j] * inv;
}

// ---------------------------------------------------------------------------
__global__ __launch_bounds__(128) void zq_kernel(const float* __restrict__ Z,
                                                 float* __restrict__ out) {
    int r = blockIdx.x;
    int t = threadIdx.x;
    int j = g_idx[r];
    const float* zr = Z    + (size_t)r * E_DIM;
    const float* cr = g_cb + (size_t)j * E_DIM;
    float* o = out + OFF_ZQ + (size_t)r * E_DIM;

    float dot = 0.0f, nc = 0.0f, nz = 0.0f;
    #pragma unroll
    for (int i = t; i < E_DIM; i += 128) {
        float zv = zr[i];
        float cv = cr[i];
        o[i] = zv + (cv - zv);
        dot += zv * cv;
        nc  += cv * cv;
        nz  += zv * zv;
    }
    __shared__ float sd_[128], sc_[128], sz_[128];
    sd_[t] = dot; sc_[t] = nc; sz_[t] = nz;
    __syncthreads();
    for (int s = 64; s > 0; s >>= 1) {
        if (t < s) { sd_[t] += sd_[t + s]; sc_[t] += sc_[t + s]; sz_[t] += sz_[t + s]; }
        __syncthreads();
    }
    if (t == 0) {
        g_cos[r] = sd_[0] / (fmaxf(sqrtf(sc_[0]), 1e-8f) * fmaxf(sqrtf(sz_[0]), 1e-8f));
    }
}

// ---------------------------------------------------------------------------
__global__ __launch_bounds__(256) void finalize_kernel(float* __restrict__ out) {
    int t = threadIdx.x;
    __shared__ float s1[256], s2[256], s3[256];

    float kl = 0.0f, ent = 0.0f, cs = 0.0f;
    const float invM  = 1.0f / (float)M_ROWS;
    const float invNE = 1.0f / (float)N_E;
    for (int j = t; j < N_E; j += 256) {
        float em = (float)g_counts[j] * invM;
        kl  += em * logf(invNE / (em + 1e-6f));
        ent += em * logf(em + 1e-6f);
    }
    for (int j = t; j < M_ROWS; j += 256) cs += g_cos[j];

    s1[t] = kl; s2[t] = ent; s3[t] = cs;
    __syncthreads();
    for (int s = 128; s > 0; s >>= 1) {
        if (t < s) { s1[t] += s1[t + s]; s2[t] += s2[t + s]; s3[t] += s3[t + s]; }
        __syncthreads();
    }
    if (t == 0) {
        float mc = s3[0] * invM;
        out[0] = (1.0f - mc) + 0.25f * (1.0f - mc);
        out[1] = 0.0f;
        out[2] = -s1[0];
        out[OFF_PERP] = expf(-s2[0]);
    }
}

// ---------------------------------------------------------------------------
extern "C" void kernel_launch(void* const* d_in, const int* in_sizes, int n_in,
                              void* d_out, int out_size) {
    const float* z = (const float*)d_in[0];
    const float* w = (const float*)d_in[1];
    float* out = (float*)d_out;

    cudaFuncSetAttribute(mma_gemm_kernel,
                         cudaFuncAttributeMaxDynamicSharedMemorySize, GEMM_SMEM);

    prep_cb_kernel<<<N_E, 256>>>(w);
    prep_z_kernel<<<M_ROWS, 256>>>(z);

    dim3 grid(N_E / BN, M_ROWS / BM);      // (64, 64)
    mma_gemm_kernel<<<grid, 256, GEMM_SMEM>>>(out);

    softmax_kernel<<<M_ROWS, 256>>>(out);

    zq_kernel<<<M_ROWS, 128>>>(z, out);
    finalize_kernel<<<1, 256>>>(out);
}

// round 10
// speedup vs baseline: 5.2455x; 1.0315x over previous
#include <cuda_runtime.h>
#include <cuda_bf16.h>
#include <math.h>
#include <stdint.h>

// Problem constants
#define M_ROWS 8192      // B*H*W
#define N_E    8192
#define E_DIM  512

// Output layout (flattened tuple, fp32)
#define OFF_PROB ((size_t)3)
#define OFF_D    (OFF_PROB + (size_t)M_ROWS * N_E)
#define OFF_ZQ   (OFF_D    + (size_t)M_ROWS * N_E)
#define OFF_PERP (OFF_ZQ   + (size_t)M_ROWS * E_DIM)
#define OFF_MINE (OFF_PERP + 1)      // divisible by 4 -> float4 stores legal
#define OFF_IDX  (OFF_MINE + (size_t)M_ROWS * N_E)

// ---------------------------------------------------------------------------
// Device scratch (no dynamic allocation allowed)
// ---------------------------------------------------------------------------
static __device__ float g_cb[(size_t)N_E * E_DIM];
static __device__ float g_cbnorm[N_E];
static __device__ float g_znorm[M_ROWS];
static __device__ int   g_idx[M_ROWS];
static __device__ int   g_counts[N_E];
static __device__ float g_cos[M_ROWS];
// bf16 hi/lo splits for tensor-core GEMM
static __device__ __align__(16) __nv_bfloat16 g_zhi[(size_t)M_ROWS * E_DIM];
static __device__ __align__(16) __nv_bfloat16 g_zlo[(size_t)M_ROWS * E_DIM];
static __device__ __align__(16) __nv_bfloat16 g_bhi[(size_t)N_E   * E_DIM];
static __device__ __align__(16) __nv_bfloat16 g_blo[(size_t)N_E   * E_DIM];

// ---------------------------------------------------------------------------
// PTX helpers (base ISA only: mma.sync / ldmatrix / cp.async)
// ---------------------------------------------------------------------------
__device__ __forceinline__ uint32_t smem_u32(const void* p) {
    uint32_t a;
    asm("{ .reg .u64 t; cvta.to.shared.u64 t, %1; cvt.u32.u64 %0, t; }"
        : "=r"(a) : "l"(p));
    return a;
}
__device__ __forceinline__ void cp16(uint32_t saddr, const void* g) {
    asm volatile("cp.async.cg.shared.global [%0], [%1], 16;"
                 :: "r"(saddr), "l"(g) : "memory");
}
__device__ __forceinline__ void ldsm4(uint32_t* r, uint32_t addr) {
    asm volatile("ldmatrix.sync.aligned.m8n8.x4.shared.b16 {%0,%1,%2,%3}, [%4];"
                 : "=r"(r[0]), "=r"(r[1]), "=r"(r[2]), "=r"(r[3]) : "r"(addr));
}
__device__ __forceinline__ void mma_bf16(float* c, const uint32_t* a, const uint32_t* b) {
    asm volatile(
        "mma.sync.aligned.m16n8k16.row.col.f32.bf16.bf16.f32 "
        "{%0,%1,%2,%3}, {%4,%5,%6,%7}, {%8,%9}, {%0,%1,%2,%3};"
        : "+f"(c[0]), "+f"(c[1]), "+f"(c[2]), "+f"(c[3])
        : "r"(a[0]), "r"(a[1]), "r"(a[2]), "r"(a[3]), "r"(b[0]), "r"(b[1]));
}

// ---------------------------------------------------------------------------
// Codebook prep: cb = w/||w||, cb_norm = ||cb||, bf16 hi/lo split
// ---------------------------------------------------------------------------
__global__ __launch_bounds__(256) void prep_cb_kernel(const float* __restrict__ w) {
    int r = blockIdx.x;
    int t = threadIdx.x;
    const float* row = w + (size_t)r * E_DIM;
    float v0 = row[t];
    float v1 = row[t + 256];

    __shared__ float sm[256];
    sm[t] = v0 * v0 + v1 * v1;
    __syncthreads();
    #pragma unroll
    for (int s = 128; s > 0; s >>= 1) {
        if (t < s) sm[t] += sm[t + s];
        __syncthreads();
    }
    float norm = sqrtf(sm[0]);
    __syncthreads();

    float c0 = v0 / norm;
    float c1 = v1 / norm;
    size_t base = (size_t)r * E_DIM;
    g_cb[base + t]       = c0;
    g_cb[base + t + 256] = c1;

    __nv_bfloat16 h0 = __float2bfloat16(c0);
    __nv_bfloat16 h1 = __float2bfloat16(c1);
    g_bhi[base + t]       = h0;
    g_bhi[base + t + 256] = h1;
    g_blo[base + t]       = __float2bfloat16(c0 - __bfloat162float(h0));
    g_blo[base + t + 256] = __float2bfloat16(c1 - __bfloat162float(h1));

    sm[t] = c0 * c0 + c1 * c1;
    __syncthreads();
    #pragma unroll
    for (int s = 128; s > 0; s >>= 1) {
        if (t < s) sm[t] += sm[t + s];
        __syncthreads();
    }
    if (t == 0) g_cbnorm[r] = sqrtf(sm[0]);
}

// ---------------------------------------------------------------------------
// z prep: row norms + bf16 hi/lo split (+ counts zeroing folded in)
// ---------------------------------------------------------------------------
__global__ __launch_bounds__(256) void prep_z_kernel(const float* __restrict__ z) {
    int r = blockIdx.x;
    int t = threadIdx.x;
    const float* row = z + (size_t)r * E_DIM;
    float v0 = row[t];
    float v1 = row[t + 256];

    size_t base = (size_t)r * E_DIM;
    __nv_bfloat16 h0 = __float2bfloat16(v0);
    __nv_bfloat16 h1 = __float2bfloat16(v1);
    g_zhi[base + t]       = h0;
    g_zhi[base + t + 256] = h1;
    g_zlo[base + t]       = __float2bfloat16(v0 - __bfloat162float(h0));
    g_zlo[base + t + 256] = __float2bfloat16(v1 - __bfloat162float(h1));

    if (r < N_E / 256) g_counts[r * 256 + t] = 0;   // 8192 rows cover 8192 counts

    __shared__ float sm[256];
    sm[t] = v0 * v0 + v1 * v1;
    __syncthreads();
    #pragma unroll
    for (int s = 128; s > 0; s >>= 1) {
        if (t < s) sm[t] += sm[t + s];
        __syncthreads();
    }
    if (t == 0) g_znorm[r] = sqrtf(sm[0]);
}

// ---------------------------------------------------------------------------
// mma.sync GEMM (3-term bf16 split): tile 128x128, K chunks of 32,
// 3-stage cp.async pipeline, loads issued 2 chunks ahead.
// Ordering: wait_group (own copies) -> __syncthreads -> issue load -> compute.
// XOR swizzle (c ^= row>>1) on 64B rows. 96KB smem/CTA -> 2 CTAs/SM.
// min_encodings zeroing INTERLEAVED into mainloop (1 float4/thread/chunk):
// stores drain behind MMA work instead of serializing after the tail wave.
// ---------------------------------------------------------------------------
#define BM 128
#define BN 128
#define KC 32
#define NCHUNK (E_DIM / KC)        // 16
#define ROWB 64                    // bytes per 32-bf16 row (no pad)
#define ARR_SZ (128 * ROWB)        // 8192
#define STAGE_SZ (4 * ARR_SZ)      // 32768
#define NSTAGE 3
#define GEMM_SMEM (NSTAGE * STAGE_SZ)  // 98304

// swizzled byte offset within one array for (row, c16) ; c16 in 0..3
__device__ __forceinline__ uint32_t swz(uint32_t row, uint32_t c16) {
    return row * ROWB + (((c16 ^ (row >> 1)) & 3u) << 4);
}

__global__ __launch_bounds__(256, 2) void mma_gemm_kernel(float* __restrict__ out) {
    extern __shared__ char smem[];
    const uint32_t sbase = smem_u32(smem);
    const int tid = threadIdx.x;
    const int lane = tid & 31;
    const int wid = tid >> 5;
    const int wm = wid & 3;        // m-quadrant: 32 rows each
    const int wn = wid >> 2;       // n-half: 64 cols each
    const int r0 = blockIdx.y * BM;
    const int c0 = blockIdx.x * BN;

    float acc[2][8][4];
    #pragma unroll
    for (int a = 0; a < 2; a++)
        #pragma unroll
        for (int b = 0; b < 8; b++)
            #pragma unroll
            for (int e = 0; e < 4; e++) acc[a][b][e] = 0.0f;

    // ---- chunk loader (cp.async): 4 arrays x 128 rows x 4 x 16B ----
    auto load_chunk = [&](int c, int stage) {
        uint32_t sb = sbase + (uint32_t)stage * STAGE_SZ;
        #pragma unroll
        for (int i = 0; i < 2; i++) {
            int slot = tid + i * 256;      // 0..511
            uint32_t row = (uint32_t)slot >> 2;
            uint32_t u   = (uint32_t)slot & 3;
            uint32_t so = swz(row, u);
            size_t ga = (size_t)(r0 + row) * E_DIM + c * KC + u * 8;
            size_t gb = (size_t)(c0 + row) * E_DIM + c * KC + u * 8;
            cp16(sb + so,              g_zhi + ga);
            cp16(sb + ARR_SZ + so,     g_zlo + ga);
            cp16(sb + 2 * ARR_SZ + so, g_bhi + gb);
            cp16(sb + 3 * ARR_SZ + so, g_blo + gb);
        }
        asm volatile("cp.async.commit_group;" ::: "memory");
    };

    // per-lane fragment addressing (swizzle XOR is invariant under +16 rows)
    const uint32_t rowA = (uint32_t)(wm * 32 + (lane & 15));
    const uint32_t rowB = (uint32_t)(wn * 64 + (lane & 7) + ((lane >> 4) << 3));
    const uint32_t xA = (rowA >> 1) & 3u;
    const uint32_t xB = (rowB >> 1) & 3u;
    const uint32_t cA0 = (uint32_t)(lane >> 4);        // 0..1
    const uint32_t cB0 = (uint32_t)((lane >> 3) & 1);  // 0..1
    const uint32_t aBase = rowA * ROWB;
    const uint32_t bBase = rowB * ROWB;

    auto compute = [&](int stage) {
        uint32_t sb = sbase + (uint32_t)stage * STAGE_SZ;
        uint32_t Ahi = sb;
        uint32_t Alo = sb + ARR_SZ;
        uint32_t Bhi = sb + 2 * ARR_SZ;
        uint32_t Blo = sb + 3 * ARR_SZ;
        #pragma unroll
        for (int ks = 0; ks < 2; ks++) {
            uint32_t aOff = aBase + (((cA0 + 2 * ks) ^ xA) & 3u) * 16;
            uint32_t bOff = bBase + (((cB0 + 2 * ks) ^ xB) & 3u) * 16;

            uint32_t ah[2][4], al[2][4];
            ldsm4(ah[0], Ahi + aOff);
            ldsm4(ah[1], Ahi + aOff + 16 * ROWB);
            ldsm4(al[0], Alo + aOff);
            ldsm4(al[1], Alo + aOff + 16 * ROWB);

            uint32_t bh[2][4], bl[2][4];
            ldsm4(bh[0], Bhi + bOff);
            ldsm4(bl[0], Blo + bOff);

            #pragma unroll
            for (int np = 0; np < 4; np++) {
                const int cur = np & 1;
                const int nxt = cur ^ 1;
                if (np < 3) {   // prefetch next B tile while doing MMAs
                    ldsm4(bh[nxt], Bhi + bOff + (np + 1) * 16 * ROWB);
                    ldsm4(bl[nxt], Blo + bOff + (np + 1) * 16 * ROWB);
                }
                #pragma unroll
                for (int mt = 0; mt < 2; mt++)
                    #pragma unroll
                    for (int s = 0; s < 2; s++)
                        mma_bf16(acc[mt][np * 2 + s], ah[mt], bh[cur] + 2 * s);  // hi*hi
                #pragma unroll
                for (int mt = 0; mt < 2; mt++)
                    #pragma unroll
                    for (int s = 0; s < 2; s++)
                        mma_bf16(acc[mt][np * 2 + s], al[mt], bh[cur] + 2 * s);  // lo*hi
                #pragma unroll
                for (int mt = 0; mt < 2; mt++)
                    #pragma unroll
                    for (int s = 0; s < 2; s++)
                        mma_bf16(acc[mt][np * 2 + s], ah[mt], bl[cur] + 2 * s);  // hi*lo
            }
        }
    };

    // min_encodings tile zeroing, one slice per chunk (float4: OFF_MINE%4==0)
    float* MINE = out + OFF_MINE;
    const int zrow = wid;              // 8 rows per slice, warp per row
    const int zcol = lane * 4;

    // ---- 3-stage pipelined mainloop, loads 2 chunks ahead ----
    load_chunk(0, 0);
    load_chunk(1, 1);
    #pragma unroll 1
    for (int c = 0; c < NCHUNK; c++) {
        if (c + 1 < NCHUNK) {
            asm volatile("cp.async.wait_group 1;" ::: "memory");  // chunk c done
        } else {
            asm volatile("cp.async.wait_group 0;" ::: "memory");
        }
        __syncthreads();   // chunk c visible to all; stage (c+2)%3 reusable
        if (c + 2 < NCHUNK) load_chunk(c + 2, (c + 2) % NSTAGE);
        // zero slice c: rows [c*8, c*8+8) of this CTA's mine tile
        {
            float4 z4 = make_float4(0.f, 0.f, 0.f, 0.f);
            *reinterpret_cast<float4*>(
                MINE + (size_t)(r0 + c * 8 + zrow) * N_E + c0 + zcol) = z4;
        }
        compute(c % NSTAGE);
    }

    // ---- epilogue: scale + scalar stores (OFF_D only 4B-aligned) ----
    float* D = out + OFF_D;
    const int gr = lane >> 2;
    const int gc = (lane & 3) * 2;
    #pragma unroll
    for (int mt = 0; mt < 2; mt++) {
        int rA = r0 + wm * 32 + mt * 16 + gr;
        int rB = rA + 8;
        float znA = g_znorm[rA];
        float znB = g_znorm[rB];
        #pragma unroll
        for (int n8 = 0; n8 < 8; n8++) {
            int cc = c0 + wn * 64 + n8 * 8 + gc;
            float cn0 = g_cbnorm[cc];
            float cn1 = g_cbnorm[cc + 1];
            float* a4 = acc[mt][n8];
            D[(size_t)rA * N_E + cc]     = a4[0] / (znA * cn0 + 1e-6f);
            D[(size_t)rA * N_E + cc + 1] = a4[1] / (znA * cn1 + 1e-6f);
            D[(size_t)rB * N_E + cc]     = a4[2] / (znB * cn0 + 1e-6f);
            D[(size_t)rB * N_E + cc + 1] = a4[3] / (znB * cn1 + 1e-6f);
        }
    }
}

// ---------------------------------------------------------------------------
// Polynomial exp on [-1,1] (degree-10 Taylor, FMA pipe; avoids MUFU wall)
// ---------------------------------------------------------------------------
__device__ __forceinline__ float exp_poly(float x) {
    const float c10 = 2.7557319e-7f, c9 = 2.7557319e-6f, c8 = 2.4801587e-5f;
    const float c7 = 1.9841270e-4f,  c6 = 1.3888889e-3f, c5 = 8.3333333e-3f;
    const float c4 = 4.1666668e-2f,  c3 = 1.6666667e-1f, c2 = 0.5f;
    float p = c10;
    p = fmaf(p, x, c9);
    p = fmaf(p, x, c8);
    p = fmaf(p, x, c7);
    p = fmaf(p, x, c6);
    p = fmaf(p, x, c5);
    p = fmaf(p, x, c4);
    p = fmaf(p, x, c3);
    p = fmaf(p, x, c2);
    p = fmaf(p, x, 1.0f);
    p = fmaf(p, x, 1.0f);
    return p;
}

// ---------------------------------------------------------------------------
// Fused per-row: argmax (first-index tie-break), histogram, idx output,
// softmax (poly exp, shift-free: d in [-1,1]), single one-hot 1.0 scatter
// (zeros already laid down by the GEMM mainloop).
// ---------------------------------------------------------------------------
__global__ __launch_bounds__(256) void softmax_kernel(float* __restrict__ out) {
    __shared__ float sred[256];
    __shared__ int   sidx[256];

    int r = blockIdx.x;
    int t = threadIdx.x;
    const float* drow = out + OFF_D + (size_t)r * N_E;

    float e[32];
    float best = -2.0f;
    int bi = 0;
    float sum = 0.0f;
    #pragma unroll
    for (int j = 0; j < 32; j++) {
        int i = t + j * 256;
        float v = drow[i];
        if (v > best) { best = v; bi = i; }   // j ascending => first index kept
        float ev = exp_poly(v);
        e[j] = ev;
        sum += ev;
    }
    sred[t] = best; sidx[t] = bi;
    __syncthreads();
    for (int s = 128; s > 0; s >>= 1) {
        if (t < s) {
            float v = sred[t + s]; int ii = sidx[t + s];
            if (v > sred[t] || (v == sred[t] && ii < sidx[t])) {
                sred[t] = v; sidx[t] = ii;
            }
        }
        __syncthreads();
    }
    if (t == 0) {
        int idx = sidx[0];
        g_idx[r] = idx;
        atomicAdd(&g_counts[idx], 1);
        out[OFF_IDX + r] = (float)idx;
        out[OFF_MINE + (size_t)r * N_E + idx] = 1.0f;
    }
    __syncthreads();

    sred[t] = sum;
    __syncthreads();
    for (int s = 128; s > 0; s >>= 1) {
        if (t < s) sred[t] += sred[t + s];
        __syncthreads();
    }
    float inv = 1.0f / sred[0];

    float* prow = out + OFF_PROB + (size_t)r * N_E;
    #pragma unroll
    for (int j = 0; j < 32; j++) prow[t + j * 256] = e[j] * inv;
}

// ---------------------------------------------------------------------------
__global__ __launch_bounds__(128) void zq_kernel(const float* __restrict__ Z,
                                                 float* __restrict__ out) {
    int r = blockIdx.x;
    int t = threadIdx.x;
    int j = g_idx[r];
    const float* zr = Z    + (size_t)r * E_DIM;
    const float* cr = g_cb + (size_t)j * E_DIM;
    float* o = out + OFF_ZQ + (size_t)r * E_DIM;

    float dot = 0.0f, nc = 0.0f, nz = 0.0f;
    #pragma unroll
    for (int i = t; i < E_DIM; i += 128) {
        float zv = zr[i];
        float cv = cr[i];
        o[i] = zv + (cv - zv);
        dot += zv * cv;
        nc  += cv * cv;
        nz  += zv * zv;
    }
    __shared__ float sd_[128], sc_[128], sz_[128];
    sd_[t] = dot; sc_[t] = nc; sz_[t] = nz;
    __syncthreads();
    for (int s = 64; s > 0; s >>= 1) {
        if (t < s) { sd_[t] += sd_[t + s]; sc_[t] += sc_[t + s]; sz_[t] += sz_[t + s]; }
        __syncthreads();
    }
    if (t == 0) {
        g_cos[r] = sd_[0] / (fmaxf(sqrtf(sc_[0]), 1e-8f) * fmaxf(sqrtf(sz_[0]), 1e-8f));
    }
}

// ---------------------------------------------------------------------------
__global__ __launch_bounds__(256) void finalize_kernel(float* __restrict__ out) {
    int t = threadIdx.x;
    __shared__ float s1[256], s2[256], s3[256];

    float kl = 0.0f, ent = 0.0f, cs = 0.0f;
    const float invM  = 1.0f / (float)M_ROWS;
    const float invNE = 1.0f / (float)N_E;
    for (int j = t; j < N_E; j += 256) {
        float em = (float)g_counts[j] * invM;
        kl  += em * logf(invNE / (em + 1e-6f));
        ent += em * logf(em + 1e-6f);
    }
    for (int j = t; j < M_ROWS; j += 256) cs += g_cos[j];

    s1[t] = kl; s2[t] = ent; s3[t] = cs;
    __syncthreads();
    for (int s = 128; s > 0; s >>= 1) {
        if (t < s) { s1[t] += s1[t + s]; s2[t] += s2[t + s]; s3[t] += s3[t + s]; }
        __syncthreads();
    }
    if (t == 0) {
        float mc = s3[0] * invM;
        out[0] = (1.0f - mc) + 0.25f * (1.0f - mc);
        out[1] = 0.0f;
        out[2] = -s1[0];
        out[OFF_PERP] = expf(-s2[0]);
    }
}

// ---------------------------------------------------------------------------
extern "C" void kernel_launch(void* const* d_in, const int* in_sizes, int n_in,
                              void* d_out, int out_size) {
    const float* z = (const float*)d_in[0];
    const float* w = (const float*)d_in[1];
    float* out = (float*)d_out;

    cudaFuncSetAttribute(mma_gemm_kernel,
                         cudaFuncAttributeMaxDynamicSharedMemorySize, GEMM_SMEM);

    prep_cb_kernel<<<N_E, 256>>>(w);
    prep_z_kernel<<<M_ROWS, 256>>>(z);

    dim3 grid(N_E / BN, M_ROWS / BM);      // (64, 64)
    mma_gemm_kernel<<<grid, 256, GEMM_SMEM>>>(out);

    softmax_kernel<<<M_ROWS, 256>>>(out);

    zq_kernel<<<M_ROWS, 128>>>(z, out);
    finalize_kernel<<<1, 256>>>(out);
}